// round 3
// baseline (speedup 1.0000x reference)
#include <cuda_runtime.h>
#include <math.h>

#define Bn 2
#define C 64
#define H 256
#define W 256
#define S (H*W)
#define HEADS 4
#define HD 16

// Scratch (device globals -- no allocations allowed)
__device__ float g_conv[Bn*C*S];          // deform-conv output [B,C,S], fp32
__device__ float g_G[Bn*HEADS*HD*HD];     // raw gram q.k
__device__ float g_qn2[Bn*HEADS*HD];      // sum q^2 per row
__device__ float g_kn2[Bn*HEADS*HD];      // sum k^2 per row

__device__ __forceinline__ unsigned f2tf32(float x) {
    unsigned u; asm("cvt.rna.tf32.f32 %0, %1;" : "=r"(u) : "f"(x)); return u;
}

// ---------------------------------------------------------------------------
__global__ void zero_kernel() {
    int tid = threadIdx.x;
    for (int t = tid; t < Bn*HEADS*HD*HD; t += 256) g_G[t] = 0.f;
    for (int t = tid; t < Bn*HEADS*HD;    t += 256) { g_qn2[t] = 0.f; g_kn2[t] = 0.f; }
}

// ---------------------------------------------------------------------------
// Deformable 3x3 conv as implicit GEMM on tensor cores (tf32 mma.sync).
//   out[o, p] = sum_{ck=0..575} w[o, ck] * s[ck, p]
// Block: 128 px x 64 out-ch, 256 threads = 8 warps (4 o-warps x 2 px-warps),
// each warp: 16 o x 64 px via m16n8k8 fragments.
// K chunks: 4 channels x 9 taps = 36 rows, padded to 40 (5 k8-steps).
#define SP 136   // s row stride (floats): 136 % 32 == 8 -> conflict-free frags
#define WP 72    // w row stride: 72 % 32 == 8
__global__ __launch_bounds__(256, 2) void deform_conv_kernel(
    const float* __restrict__ clone, const float* __restrict__ u,
    const float* __restrict__ v, const float* __restrict__ weight)
{
    __shared__ float s_s[40][SP];   // [ck_local][px]  (tf32 bits)
    __shared__ float s_w[40][WP];   // [ck_local][o]   (tf32 bits)

    int tid  = threadIdx.x;
    int lane = tid & 31;
    int warp = tid >> 5;
    int g = lane >> 2;     // fragment "groupID"
    int cq = lane & 3;     // fragment "threadID_in_group"
    int wo = warp >> 1;    // o-warp: 0..3 -> o0 = wo*16
    int wp = warp & 1;     // px-warp: 0..1 -> px0 = wp*64
    int o0 = wo * 16, px0 = wp * 64;

    int pix0  = blockIdx.x * 128;
    int b     = pix0 >> 16;
    int pbase = pix0 & (S - 1);

    // ---- per-thread pixel params (pixel = pbase + (tid&127)) ----
    int pl = tid & 127;
    int p  = pbase + pl;
    int y = p >> 8, x = p & 255;
    float py = (float)y + v[b*S + p];
    float px_ = (float)x + u[b*S + p];
    float fy = floorf(py), fx = floorf(px_);
    int y0 = (int)fy, x0 = (int)fx;
    float wy = py - fy, wx = px_ - fx;
    int  rowoff[4]; bool vy[4], vx[4];
    #pragma unroll
    for (int r = 0; r < 4; r++) {
        int yy = y0 - 1 + r;
        vy[r] = ((unsigned)yy < (unsigned)H);
        rowoff[r] = yy * W;
    }
    #pragma unroll
    for (int q = 0; q < 4; q++) vx[q] = ((unsigned)(x0 - 1 + q) < (unsigned)W);

    // ---- zero pad rows (rows 36..39) once ----
    for (int t = tid; t < 4*SP; t += 256) s_s[36 + t/SP][t%SP] = 0.f;
    for (int t = tid; t < 4*WP; t += 256) s_w[36 + t/WP][t%WP] = 0.f;

    float acc[8][4];
    #pragma unroll
    for (int nt = 0; nt < 8; nt++)
        #pragma unroll
        for (int j = 0; j < 4; j++) acc[nt][j] = 0.f;

    for (int chunk = 0; chunk < 16; ++chunk) {
        int cb = chunk * 4;
        __syncthreads();   // previous mainloop done (and pads visible, 1st iter)

        // stage w: rows 0..35  ([ck][o]), tf32-rounded
        for (int t = tid; t < 36*64; t += 256) {
            int ck = t >> 6, o = t & 63;
            int c = cb + ck / 9, k = ck - (ck/9)*9;
            unsigned uw = f2tf32(weight[(o*C + c)*9 + k]);
            s_w[ck][o] = __uint_as_float(uw);
        }
        // gather + bilinear tap expansion: this thread's pixel, 2 channels
        #pragma unroll
        for (int r2 = 0; r2 < 2; r2++) {
            int cl = (tid >> 7) + 2*r2;    // 0..3
            const float* plane = clone + ((b*C + cb + cl) << 16);
            float patch[4][4];
            #pragma unroll
            for (int r = 0; r < 4; r++)
                #pragma unroll
                for (int q = 0; q < 4; q++)
                    patch[r][q] = (vy[r] && vx[q]) ? __ldg(plane + rowoff[r] + (x0 - 1 + q)) : 0.f;
            float hx[4][3];
            #pragma unroll
            for (int r = 0; r < 4; r++)
                #pragma unroll
                for (int kx = 0; kx < 3; kx++)
                    hx[r][kx] = patch[r][kx] + wx*(patch[r][kx+1] - patch[r][kx]);
            #pragma unroll
            for (int ky = 0; ky < 3; ky++)
                #pragma unroll
                for (int kx = 0; kx < 3; kx++) {
                    float sval = hx[ky][kx] + wy*(hx[ky+1][kx] - hx[ky][kx]);
                    s_s[cl*9 + ky*3 + kx][pl] = __uint_as_float(f2tf32(sval));
                }
        }
        __syncthreads();

        // mma mainloop: 5 k8-steps over 40 rows
        #pragma unroll
        for (int ks = 0; ks < 5; ks++) {
            int kr = ks * 8;
            unsigned a0 = __float_as_uint(s_w[kr + cq    ][o0 + g    ]);
            unsigned a1 = __float_as_uint(s_w[kr + cq    ][o0 + g + 8]);
            unsigned a2 = __float_as_uint(s_w[kr + cq + 4][o0 + g    ]);
            unsigned a3 = __float_as_uint(s_w[kr + cq + 4][o0 + g + 8]);
            #pragma unroll
            for (int nt = 0; nt < 8; nt++) {
                int n0 = px0 + nt*8;
                unsigned b0 = __float_as_uint(s_s[kr + cq    ][n0 + g]);
                unsigned b1 = __float_as_uint(s_s[kr + cq + 4][n0 + g]);
                asm volatile(
                    "mma.sync.aligned.m16n8k8.row.col.f32.tf32.tf32.f32 "
                    "{%0,%1,%2,%3}, {%4,%5,%6,%7}, {%8,%9}, {%0,%1,%2,%3};"
                    : "+f"(acc[nt][0]), "+f"(acc[nt][1]), "+f"(acc[nt][2]), "+f"(acc[nt][3])
                    : "r"(a0), "r"(a1), "r"(a2), "r"(a3), "r"(b0), "r"(b1));
            }
        }
    }

    // epilogue: fragment -> g_conv
    int o_a = o0 + g, o_b = o_a + 8;
    #pragma unroll
    for (int nt = 0; nt < 8; nt++) {
        int pxo = pbase + px0 + nt*8 + 2*cq;
        *(float2*)&g_conv[(b*C + o_a)*S + pxo] = make_float2(acc[nt][0], acc[nt][1]);
        *(float2*)&g_conv[(b*C + o_b)*S + pxo] = make_float2(acc[nt][2], acc[nt][3]);
    }
}

// ---------------------------------------------------------------------------
// Gram + norms: per (b,h) compute G[16][16] = q_i . k_j over S, plus sum q^2,
// sum k^2 per row. Split S into 32 slices of 2048; atomic partial reduction.
__global__ __launch_bounds__(256) void dots_kernel(const float* __restrict__ xg) {
    __shared__ float qs[16][260];
    __shared__ float ks[16][260];
    __shared__ float s_nq[16], s_nk[16];

    int tid = threadIdx.x;
    int bh  = blockIdx.x >> 5;
    int sl  = blockIdx.x & 31;
    int b   = bh >> 2, hh = bh & 3;
    int i = tid >> 4, j = tid & 15;
    int s0 = sl * 2048;

    if (tid < 16) { s_nq[tid] = 0.f; s_nk[tid] = 0.f; }

    float g = 0.f, nqp = 0.f, nkp = 0.f;
    for (int ch = 0; ch < 8; ++ch) {
        __syncthreads();
        int sbase = s0 + ch*256;
        #pragma unroll
        for (int e = 0; e < 8; ++e) {
            int lin = tid + e*256;          // float4 unit, 0..2047
            int r = lin >> 6, c4 = lin & 63;
            const float* src = (r < 16)
                ? (xg     + (b*C + hh*HD + r)*S)
                : (g_conv + (b*C + hh*HD + (r-16))*S);
            float4 val = *(const float4*)(src + sbase + c4*4);
            float* dst = (r < 16) ? &qs[r][c4*4] : &ks[r-16][c4*4];
            dst[0] = val.x; dst[1] = val.y; dst[2] = val.z; dst[3] = val.w;
        }
        __syncthreads();
        #pragma unroll 8
        for (int s = 0; s < 256; s += 4) {
            float4 qv = *(const float4*)&qs[i][s];
            float4 kv = *(const float4*)&ks[j][s];
            g += qv.x*kv.x; g += qv.y*kv.y; g += qv.z*kv.z; g += qv.w*kv.w;
        }
        #pragma unroll 4
        for (int s = j; s < 256; s += 16) { float q0 = qs[i][s]; nqp += q0*q0; }
        #pragma unroll 4
        for (int s = i; s < 256; s += 16) { float k0 = ks[j][s]; nkp += k0*k0; }
    }
    atomicAdd(&g_G[bh*256 + i*16 + j], g);
    atomicAdd(&s_nq[i], nqp);
    atomicAdd(&s_nk[j], nkp);
    __syncthreads();
    if (tid < 16)       atomicAdd(&g_qn2[bh*16 + tid], s_nq[tid]);
    else if (tid < 32)  atomicAdd(&g_kn2[bh*16 + tid-16], s_nk[tid-16]);
}

// ---------------------------------------------------------------------------
// Fused softmax + out. Block = (b,h) x 1024-px tile; thread owns one float4
// column and accumulates all 16 output rows in registers.
__global__ __launch_bounds__(256, 2) void out_kernel(float* __restrict__ out,
                                                     const float* __restrict__ temp) {
    __shared__ float s_attn[16][16];
    int tid = threadIdx.x;
    int bh  = blockIdx.x >> 6;     // 64 tiles of 1024 px
    int tile = blockIdx.x & 63;
    int b = bh >> 2, hh = bh & 3;

    // softmax prologue
    {
        int i = tid >> 4, j = tid & 15;
        float dq = fmaxf(sqrtf(g_qn2[bh*16 + i]), 1e-12f);
        float dk = fmaxf(sqrtf(g_kn2[bh*16 + j]), 1e-12f);
        float T  = temp[hh];
        float l  = g_G[bh*256 + i*16 + j] / (dq*dk) * T;
        float m = l;
        #pragma unroll
        for (int off = 8; off > 0; off >>= 1)
            m = fmaxf(m, __shfl_xor_sync(0xffffffffu, m, off, 16));
        float e = expf(l - m);
        float ssum = e;
        #pragma unroll
        for (int off = 8; off > 0; off >>= 1)
            ssum += __shfl_xor_sync(0xffffffffu, ssum, off, 16);
        s_attn[i][j] = e / ssum;
    }
    __syncthreads();

    int s = tile*1024 + tid*4;
    float4 acc[16];
    #pragma unroll
    for (int o = 0; o < 16; o++) acc[o] = make_float4(0.f, 0.f, 0.f, 0.f);

    #pragma unroll
    for (int d = 0; d < 16; d++) {
        float4 kvv = *(const float4*)&g_conv[(b*C + hh*HD + d)*S + s];
        #pragma unroll
        for (int o = 0; o < 16; o++) {
            float a = s_attn[o][d];
            acc[o].x += a*kvv.x; acc[o].y += a*kvv.y;
            acc[o].z += a*kvv.z; acc[o].w += a*kvv.w;
        }
    }
    #pragma unroll
    for (int o = 0; o < 16; o++)
        *(float4*)&out[(b*C + hh*HD + o)*S + s] = acc[o];
}

// ---------------------------------------------------------------------------
extern "C" void kernel_launch(void* const* d_in, const int* in_sizes, int n_in,
                              void* d_out, int out_size) {
    const float* clone  = (const float*)d_in[0];
    const float* xg     = (const float*)d_in[1];
    const float* u      = (const float*)d_in[2];
    const float* v      = (const float*)d_in[3];
    const float* weight = (const float*)d_in[4];
    const float* temp   = (const float*)d_in[5];
    float* out = (float*)d_out;

    zero_kernel<<<1, 256>>>();
    deform_conv_kernel<<<Bn*S/128, 256>>>(clone, u, v, weight);
    dots_kernel<<<Bn*HEADS*32, 256>>>(xg);
    out_kernel<<<Bn*HEADS*64, 256>>>(out, temp);
}

// round 5
// speedup vs baseline: 1.3778x; 1.3778x over previous
#include <cuda_runtime.h>
#include <math.h>
#include <stdint.h>

#define Bn 2
#define C 64
#define H 256
#define W 256
#define S (H*W)
#define HEADS 4
#define HD 16
#define NCHUNK 32    // 32 chunks x 2 channels

typedef unsigned long long ull;

// Scratch (device globals -- no allocations allowed)
__device__ float  g_conv[Bn*C*S];           // deform-conv output [B,C,S]
__device__ float  g_G[Bn*HEADS*HD*HD];
__device__ float  g_qn2[Bn*HEADS*HD];
__device__ float  g_kn2[Bn*HEADS*HD];
__device__ __align__(16) float2 g_wsplat[NCHUNK*2*9*64];  // [chunk][cl][k][o] splatted

__device__ __forceinline__ void fma2(ull& d, ull a, ull b) {
    asm("fma.rn.f32x2 %0, %1, %2, %0;" : "+l"(d) : "l"(a), "l"(b));
}
__device__ __forceinline__ float2 unpack2(ull a) {
    float2 f; asm("mov.b64 {%0,%1}, %2;" : "=f"(f.x), "=f"(f.y) : "l"(a)); return f;
}

// ---------------------------------------------------------------------------
// Prep: splat weights into g_wsplat[chunk][cl][k][o]; block 0 zeros reductions.
__global__ void prep_kernel(const float* __restrict__ weight) {
    int t0 = blockIdx.x * 256 + threadIdx.x;
    for (int t = t0; t < NCHUNK*2*9*64; t += gridDim.x * 256) {
        int o  = t & 63;
        int k  = (t >> 6) % 9;
        int cc = t / 576;              // chunk*2 + cl  == channel index
        float wv = weight[(o*C + cc)*9 + k];
        g_wsplat[t] = make_float2(wv, wv);
    }
    if (blockIdx.x == 0) {
        int tid = threadIdx.x;
        for (int k = tid; k < Bn*HEADS*HD*HD; k += 256) g_G[k] = 0.f;
        for (int k = tid; k < Bn*HEADS*HD;    k += 256) { g_qn2[k] = 0.f; g_kn2[k] = 0.f; }
    }
}

// ---------------------------------------------------------------------------
// Deformable 3x3 conv, packed f32x2 FMA.
// Block: 128 threads, tile 256 px x 64 oc. Thread: 8 oc x 8 px-pairs.
// og = tid>>4 (o = og*8+oo), pg = tid&15 (pairs at px = pg*2 + pp*32).
__global__ __launch_bounds__(128, 2) void deform_conv_kernel(
    const float* __restrict__ clone, const float* __restrict__ u,
    const float* __restrict__ v)
{
    __shared__ float  s_s[2][9][256];   // [cl][k][px]
    __shared__ float2 s_w[2][9][64];    // [cl][k][o] splatted
    __shared__ float  s_wy[256], s_wx[256];
    __shared__ int    s_y0[256], s_x0[256];

    int tid = threadIdx.x;
    int og  = tid >> 4, pg = tid & 15;
    int pix0  = blockIdx.x * 256;
    int b     = pix0 >> 16;
    int pbase = pix0 & (S - 1);

    // ---- per-pixel params, once per block ----
    for (int i = tid; i < 256; i += 128) {
        int p = pbase + i;
        int y = p >> 8, x = p & 255;
        float py  = (float)y + v[b*S + p];
        float px_ = (float)x + u[b*S + p];
        float fy = floorf(py), fx = floorf(px_);
        s_y0[i] = (int)fy; s_x0[i] = (int)fx;
        s_wy[i] = py - fy; s_wx[i] = px_ - fx;
    }

    ull acc[8][8];
    #pragma unroll
    for (int oo = 0; oo < 8; oo++)
        #pragma unroll
        for (int pp = 0; pp < 8; pp++) acc[oo][pp] = 0ull;

    for (int chunk = 0; chunk < NCHUNK; ++chunk) {
        __syncthreads();   // params ready (iter 0) / prior mainloop done

        // ---- stage weights for this chunk (1152 float2) ----
        {
            const float2* src = &g_wsplat[chunk * 1152];
            float2* dst = &s_w[0][0][0];
            #pragma unroll
            for (int r = 0; r < 9; r++) dst[tid + r*128] = src[tid + r*128];
        }
        // ---- gather: 512 tasks = 2 ch x 256 px, 4 per thread ----
        #pragma unroll
        for (int i = 0; i < 4; i++) {
            int t  = tid + i*128;
            int cl = t >> 8, px = t & 255;
            int y0 = s_y0[px], x0 = s_x0[px];
            float wy = s_wy[px], wx = s_wx[px];
            const float* plane = clone + ((b*C + chunk*2 + cl) << 16);
            float hx[4][3];
            #pragma unroll
            for (int r = 0; r < 4; r++) {
                int yy = y0 - 1 + r;
                bool yok = ((unsigned)yy < (unsigned)H);
                const float* rowp = plane + yy*W;
                float p0, p1, p2, p3;
                p0 = (yok && ((unsigned)(x0-1) < (unsigned)W)) ? __ldg(rowp + x0-1) : 0.f;
                p1 = (yok && ((unsigned)(x0  ) < (unsigned)W)) ? __ldg(rowp + x0  ) : 0.f;
                p2 = (yok && ((unsigned)(x0+1) < (unsigned)W)) ? __ldg(rowp + x0+1) : 0.f;
                p3 = (yok && ((unsigned)(x0+2) < (unsigned)W)) ? __ldg(rowp + x0+2) : 0.f;
                hx[r][0] = p0 + wx*(p1 - p0);
                hx[r][1] = p1 + wx*(p2 - p1);
                hx[r][2] = p2 + wx*(p3 - p2);
            }
            #pragma unroll
            for (int ky = 0; ky < 3; ky++)
                #pragma unroll
                for (int kx = 0; kx < 3; kx++)
                    s_s[cl][ky*3+kx][px] = hx[ky][kx] + wy*(hx[ky+1][kx] - hx[ky][kx]);
        }
        __syncthreads();

        // ---- mainloop: packed FFMA2, 8 oc x 8 pairs per thread ----
        #pragma unroll
        for (int cl = 0; cl < 2; cl++) {
            #pragma unroll 3
            for (int k = 0; k < 9; k++) {
                ull w8[8];
                #pragma unroll
                for (int oo = 0; oo < 8; oo++)
                    w8[oo] = *(const ull*)&s_w[cl][k][og*8 + oo];
                #pragma unroll
                for (int pp = 0; pp < 8; pp++) {
                    ull sp = *(const ull*)&s_s[cl][k][pg*2 + pp*32];
                    #pragma unroll
                    for (int oo = 0; oo < 8; oo++)
                        fma2(acc[oo][pp], w8[oo], sp);
                }
            }
        }
    }

    // ---- epilogue ----
    #pragma unroll
    for (int oo = 0; oo < 8; oo++) {
        float* dst = &g_conv[(b*C + og*8 + oo)*S + pbase + pg*2];
        #pragma unroll
        for (int pp = 0; pp < 8; pp++)
            *(float2*)(dst + pp*32) = unpack2(acc[oo][pp]);
    }
}

// ---------------------------------------------------------------------------
// Gram + norms (unchanged from R1; ~20us).
__global__ __launch_bounds__(256) void dots_kernel(const float* __restrict__ xg) {
    __shared__ float qs[16][260];
    __shared__ float ks[16][260];
    __shared__ float s_nq[16], s_nk[16];

    int tid = threadIdx.x;
    int bh  = blockIdx.x >> 5;
    int sl  = blockIdx.x & 31;
    int b   = bh >> 2, hh = bh & 3;
    int i = tid >> 4, j = tid & 15;
    int s0 = sl * 2048;

    if (tid < 16) { s_nq[tid] = 0.f; s_nk[tid] = 0.f; }

    float g = 0.f, nqp = 0.f, nkp = 0.f;
    for (int ch = 0; ch < 8; ++ch) {
        __syncthreads();
        int sbase = s0 + ch*256;
        #pragma unroll
        for (int e = 0; e < 8; ++e) {
            int lin = tid + e*256;
            int r = lin >> 6, c4 = lin & 63;
            const float* src = (r < 16)
                ? (xg     + (b*C + hh*HD + r)*S)
                : (g_conv + (b*C + hh*HD + (r-16))*S);
            float4 val = *(const float4*)(src + sbase + c4*4);
            float* dst = (r < 16) ? &qs[r][c4*4] : &ks[r-16][c4*4];
            dst[0] = val.x; dst[1] = val.y; dst[2] = val.z; dst[3] = val.w;
        }
        __syncthreads();
        #pragma unroll 8
        for (int s = 0; s < 256; s += 4) {
            float4 qv = *(const float4*)&qs[i][s];
            float4 kv = *(const float4*)&ks[j][s];
            g += qv.x*kv.x; g += qv.y*kv.y; g += qv.z*kv.z; g += qv.w*kv.w;
        }
        #pragma unroll 4
        for (int s = j; s < 256; s += 16) { float q0 = qs[i][s]; nqp += q0*q0; }
        #pragma unroll 4
        for (int s = i; s < 256; s += 16) { float k0 = ks[j][s]; nkp += k0*k0; }
    }
    atomicAdd(&g_G[bh*256 + i*16 + j], g);
    atomicAdd(&s_nq[i], nqp);
    atomicAdd(&s_nk[j], nkp);
    __syncthreads();
    if (tid < 16)       atomicAdd(&g_qn2[bh*16 + tid], s_nq[tid]);
    else if (tid < 32)  atomicAdd(&g_kn2[bh*16 + tid-16], s_nk[tid-16]);
}

// ---------------------------------------------------------------------------
// Fused softmax + out.
__global__ __launch_bounds__(256, 3) void out_kernel(float* __restrict__ out,
                                                     const float* __restrict__ temp) {
    __shared__ float s_attn[16][16];
    int tid = threadIdx.x;
    int bh  = blockIdx.x >> 6;
    int tile = blockIdx.x & 63;
    int b = bh >> 2, hh = bh & 3;

    {
        int i = tid >> 4, j = tid & 15;
        float dq = fmaxf(sqrtf(g_qn2[bh*16 + i]), 1e-12f);
        float dk = fmaxf(sqrtf(g_kn2[bh*16 + j]), 1e-12f);
        float T  = temp[hh];
        float l  = g_G[bh*256 + i*16 + j] / (dq*dk) * T;
        float m = l;
        #pragma unroll
        for (int off = 8; off > 0; off >>= 1)
            m = fmaxf(m, __shfl_xor_sync(0xffffffffu, m, off, 16));
        float e = expf(l - m);
        float ssum = e;
        #pragma unroll
        for (int off = 8; off > 0; off >>= 1)
            ssum += __shfl_xor_sync(0xffffffffu, ssum, off, 16);
        s_attn[i][j] = e / ssum;
    }
    __syncthreads();

    int s = tile*1024 + tid*4;
    float4 acc[16];
    #pragma unroll
    for (int o = 0; o < 16; o++) acc[o] = make_float4(0.f, 0.f, 0.f, 0.f);

    #pragma unroll
    for (int d = 0; d < 16; d++) {
        float4 kvv = *(const float4*)&g_conv[(b*C + hh*HD + d)*S + s];
        #pragma unroll
        for (int o = 0; o < 16; o++) {
            float a = s_attn[o][d];
            acc[o].x += a*kvv.x; acc[o].y += a*kvv.y;
            acc[o].z += a*kvv.z; acc[o].w += a*kvv.w;
        }
    }
    #pragma unroll
    for (int o = 0; o < 16; o++)
        *(float4*)&out[(b*C + hh*HD + o)*S + s] = acc[o];
}

// ---------------------------------------------------------------------------
extern "C" void kernel_launch(void* const* d_in, const int* in_sizes, int n_in,
                              void* d_out, int out_size) {
    const float* clone  = (const float*)d_in[0];
    const float* xg     = (const float*)d_in[1];
    const float* u      = (const float*)d_in[2];
    const float* v      = (const float*)d_in[3];
    const float* weight = (const float*)d_in[4];
    const float* temp   = (const float*)d_in[5];
    float* out = (float*)d_out;

    prep_kernel<<<64, 256>>>(weight);
    deform_conv_kernel<<<Bn*S/256, 128>>>(clone, u, v);
    dots_kernel<<<Bn*HEADS*32, 256>>>(xg);
    out_kernel<<<Bn*HEADS*64, 256>>>(out, temp);
}

// round 6
// speedup vs baseline: 1.9587x; 1.4216x over previous
#include <cuda_runtime.h>
#include <math.h>
#include <stdint.h>

#define Bn 2
#define C 64
#define H 256
#define W 256
#define S (H*W)
#define HEADS 4
#define HD 16

#define NT 129          // winograd tiles per dim (output grid 258 = 2*129)
#define NTT (NT*NT)     // 16641 tiles
#define TS 16768        // tile-dim stride (131 * 128, padded)
#define NBLK 131        // gemm tile-blocks per (b,f)
#define GR 258          // winG rows
#define GP 260          // winG col stride

// Scratch (device globals -- no allocations allowed; statics are zero-init)
__device__ float g_conv[Bn*C*S];            // deform-conv output [B,C,S]
__device__ float g_gram[Bn*HEADS*HD*HD];
__device__ float g_qn2[Bn*HEADS*HD];
__device__ float g_kn2[Bn*HEADS*HD];
__device__ __align__(16) float g_U[16*64*64];        // [f][ci][co]
__device__ __align__(16) float g_V[Bn*16*64*TS];     // [b][f][ci][t]   137MB
__device__ __align__(16) float g_M[Bn*16*64*TS];     // [b][f][co][t]   137MB
__device__ __align__(16) float g_winG[Bn*64*GR*GP];  // dense conv on ext grid

// ---------------------------------------------------------------------------
// Prep: weight transform U = G g G^T per (ci,co); zero gram accumulators.
__global__ void prep_kernel(const float* __restrict__ weight) {
    int t = blockIdx.x*256 + threadIdx.x;        // 0..4095
    if (t < 4096) {
        int co = t & 63, ci = t >> 6;
        float g[3][3];
        #pragma unroll
        for (int k = 0; k < 9; k++) g[k/3][k%3] = weight[(co*C + ci)*9 + k];
        float q[4][3];
        #pragma unroll
        for (int kx = 0; kx < 3; kx++) {
            q[0][kx] = g[0][kx];
            q[1][kx] = 0.5f*(g[0][kx] + g[1][kx] + g[2][kx]);
            q[2][kx] = 0.5f*(g[0][kx] - g[1][kx] + g[2][kx]);
            q[3][kx] = g[2][kx];
        }
        #pragma unroll
        for (int r = 0; r < 4; r++) {
            float u0 = q[r][0];
            float u1 = 0.5f*(q[r][0] + q[r][1] + q[r][2]);
            float u2 = 0.5f*(q[r][0] - q[r][1] + q[r][2]);
            float u3 = q[r][2];
            g_U[((r*4+0)*4096) + ci*64 + co] = u0;
            g_U[((r*4+1)*4096) + ci*64 + co] = u1;
            g_U[((r*4+2)*4096) + ci*64 + co] = u2;
            g_U[((r*4+3)*4096) + ci*64 + co] = u3;
        }
    }
    if (blockIdx.x == 0) {
        int tid = threadIdx.x;
        for (int k = tid; k < Bn*HEADS*HD*HD; k += 256) g_gram[k] = 0.f;
        for (int k = tid; k < Bn*HEADS*HD;    k += 256) { g_qn2[k] = 0.f; g_kn2[k] = 0.f; }
    }
}

// ---------------------------------------------------------------------------
// Input transform: V = B^T d B per 4x4 tile (stride 2, zero-padded clone).
// Block = (b*64+ci)*NT + ty; 128 threads cover 129 tx tiles.
__global__ __launch_bounds__(128) void winograd_in(const float* __restrict__ clone) {
    __shared__ float rows[4][256];
    int z  = blockIdx.x;
    int ty = z % NT;
    int bc = z / NT;                 // b*64 + ci
    int ci = bc & 63, b = bc >> 6;
    int tid = threadIdx.x;

    const float* plane = clone + ((size_t)bc << 16);
    #pragma unroll
    for (int i = 0; i < 2; i++) {
        int idx = tid + i*128;               // 0..255: (row, float4-col)
        int r = idx >> 6, c4 = idx & 63;
        int gr = 2*ty - 2 + r;
        float4 val = make_float4(0.f,0.f,0.f,0.f);
        if ((unsigned)gr < 256u) val = *(const float4*)(plane + gr*256 + c4*4);
        *(float4*)&rows[r][c4*4] = val;
    }
    __syncthreads();

    for (int tx = tid; tx < NT; tx += 128) {
        float d[4][4];
        int cbase = 2*tx - 2;
        #pragma unroll
        for (int jj = 0; jj < 4; jj++) {
            int cc = cbase + jj;
            bool ok = ((unsigned)cc < 256u);
            #pragma unroll
            for (int j = 0; j < 4; j++) d[j][jj] = ok ? rows[j][cc] : 0.f;
        }
        float t4[4][4];
        #pragma unroll
        for (int c2 = 0; c2 < 4; c2++) {
            t4[0][c2] = d[0][c2] - d[2][c2];
            t4[1][c2] = d[1][c2] + d[2][c2];
            t4[2][c2] = d[2][c2] - d[1][c2];
            t4[3][c2] = d[1][c2] - d[3][c2];
        }
        int tlin = ty*NT + tx;
        #pragma unroll
        for (int r = 0; r < 4; r++) {
            float v0 = t4[r][0] - t4[r][2];
            float v1 = t4[r][1] + t4[r][2];
            float v2 = t4[r][2] - t4[r][1];
            float v3 = t4[r][1] - t4[r][3];
            g_V[((b*16 + r*4+0)*64 + ci)*TS + tlin] = v0;
            g_V[((b*16 + r*4+1)*64 + ci)*TS + tlin] = v1;
            g_V[((b*16 + r*4+2)*64 + ci)*TS + tlin] = v2;
            g_V[((b*16 + r*4+3)*64 + ci)*TS + tlin] = v3;
        }
    }
}

// ---------------------------------------------------------------------------
// Per-frequency GEMM: M[bf][co][t] = sum_ci U[f][ci][co] * V[bf][ci][t].
// Block: 64 co x 128 t; thread: 4 co x 8 t.
__global__ __launch_bounds__(256) void winograd_gemm() {
    __shared__ float4 Vc[16][32];    // [ci_local][128 floats]
    __shared__ float4 Uc[16][16];    // [ci_local][64 floats]
    int bf = blockIdx.x / NBLK;      // b*16 + f
    int tc = blockIdx.x % NBLK;
    int f  = bf & 15;
    int t0 = tc * 128;
    int tid = threadIdx.x;
    int cg = tid >> 4, tg = tid & 15;

    float acc[4][8];
    #pragma unroll
    for (int i = 0; i < 4; i++)
        #pragma unroll
        for (int j = 0; j < 8; j++) acc[i][j] = 0.f;

    for (int ci0 = 0; ci0 < 64; ci0 += 16) {
        __syncthreads();
        {
            int r = tid >> 4, c = tid & 15;
            const float* vsrc = &g_V[(bf*64 + ci0 + r)*TS + t0];
            Vc[r][c]      = *(const float4*)(vsrc + c*4);
            Vc[r][c + 16] = *(const float4*)(vsrc + 64 + c*4);
            Uc[r][c]      = *(const float4*)&g_U[f*4096 + (ci0 + r)*64 + c*4];
        }
        __syncthreads();
        #pragma unroll
        for (int cl = 0; cl < 16; cl++) {
            float4 w  = Uc[cl][cg];
            float4 s0 = Vc[cl][tg*2];
            float4 s1 = Vc[cl][tg*2 + 1];
            acc[0][0] += w.x*s0.x; acc[0][1] += w.x*s0.y; acc[0][2] += w.x*s0.z; acc[0][3] += w.x*s0.w;
            acc[0][4] += w.x*s1.x; acc[0][5] += w.x*s1.y; acc[0][6] += w.x*s1.z; acc[0][7] += w.x*s1.w;
            acc[1][0] += w.y*s0.x; acc[1][1] += w.y*s0.y; acc[1][2] += w.y*s0.z; acc[1][3] += w.y*s0.w;
            acc[1][4] += w.y*s1.x; acc[1][5] += w.y*s1.y; acc[1][6] += w.y*s1.z; acc[1][7] += w.y*s1.w;
            acc[2][0] += w.z*s0.x; acc[2][1] += w.z*s0.y; acc[2][2] += w.z*s0.z; acc[2][3] += w.z*s0.w;
            acc[2][4] += w.z*s1.x; acc[2][5] += w.z*s1.y; acc[2][6] += w.z*s1.z; acc[2][7] += w.z*s1.w;
            acc[3][0] += w.w*s0.x; acc[3][1] += w.w*s0.y; acc[3][2] += w.w*s0.z; acc[3][3] += w.w*s0.w;
            acc[3][4] += w.w*s1.x; acc[3][5] += w.w*s1.y; acc[3][6] += w.w*s1.z; acc[3][7] += w.w*s1.w;
        }
    }
    #pragma unroll
    for (int i = 0; i < 4; i++) {
        float* mp = &g_M[(bf*64 + cg*4 + i)*TS + t0 + tg*8];
        *(float4*)mp       = make_float4(acc[i][0], acc[i][1], acc[i][2], acc[i][3]);
        *(float4*)(mp + 4) = make_float4(acc[i][4], acc[i][5], acc[i][6], acc[i][7]);
    }
}

// ---------------------------------------------------------------------------
// Output transform: Y = A^T m A (2x2) -> dense conv G on extended grid.
__global__ __launch_bounds__(128) void winograd_out() {
    int z  = blockIdx.x;
    int ty = z % NT;
    int bc = z / NT;                 // b*64 + co
    int co = bc & 63, b = bc >> 6;
    int tid = threadIdx.x;

    for (int tx = tid; tx < NT; tx += 128) {
        int tlin = ty*NT + tx;
        float m[4][4];
        #pragma unroll
        for (int f = 0; f < 16; f++)
            m[f >> 2][f & 3] = g_M[((b*16 + f)*64 + co)*TS + tlin];
        float t2[2][4];
        #pragma unroll
        for (int c2 = 0; c2 < 4; c2++) {
            t2[0][c2] = m[0][c2] + m[1][c2] + m[2][c2];
            t2[1][c2] = m[1][c2] - m[2][c2] - m[3][c2];
        }
        float y00 = t2[0][0] + t2[0][1] + t2[0][2];
        float y01 = t2[0][1] - t2[0][2] - t2[0][3];
        float y10 = t2[1][0] + t2[1][1] + t2[1][2];
        float y11 = t2[1][1] - t2[1][2] - t2[1][3];
        float* gp = &g_winG[((size_t)bc*GR + 2*ty)*GP + 2*tx];
        gp[0] = y00; gp[1] = y01; gp[GP] = y10; gp[GP+1] = y11;
    }
}

// ---------------------------------------------------------------------------
// Flow-guided bilinear resample of G -> deform conv output.
__global__ __launch_bounds__(256) void resample_kernel(
    const float* __restrict__ u, const float* __restrict__ v)
{
    int idx = blockIdx.x*256 + threadIdx.x;     // 0..131071
    int b = idx >> 16, p = idx & 65535;
    int y = p >> 8, x = p & 255;
    float py  = (float)y + v[b*S + p];
    float px_ = (float)x + u[b*S + p];
    float fy = floorf(py), fx = floorf(px_);
    int y0 = (int)fy, x0 = (int)fx;
    float wy = py - fy, wx = px_ - fx;
    // corner (yc,xc) nonzero iff yc,xc in [-1,256]; array index = coord+1
    bool r0 = ((unsigned)(y0+1) < (unsigned)GR);
    bool r1 = ((unsigned)(y0+2) < (unsigned)GR);
    bool c0 = ((unsigned)(x0+1) < (unsigned)GR);
    bool c1 = ((unsigned)(x0+2) < (unsigned)GR);
    int off = (y0+1)*GP + (x0+1);
    float w00 = (1.f-wy)*(1.f-wx), w01 = (1.f-wy)*wx;
    float w10 = wy*(1.f-wx),       w11 = wy*wx;

    const float* Gb = g_winG + (size_t)(b*64)*GR*GP;
    float* dst = &g_conv[(size_t)(b*64)*S + p];
    #pragma unroll 4
    for (int ch = 0; ch < 64; ch++) {
        const float* Gp = Gb + (size_t)ch*GR*GP;
        float g00 = (r0 && c0) ? __ldg(Gp + off)        : 0.f;
        float g01 = (r0 && c1) ? __ldg(Gp + off + 1)    : 0.f;
        float g10 = (r1 && c0) ? __ldg(Gp + off + GP)   : 0.f;
        float g11 = (r1 && c1) ? __ldg(Gp + off + GP+1) : 0.f;
        dst[(size_t)ch*S] = w00*g00 + w01*g01 + w10*g10 + w11*g11;
    }
}

// ---------------------------------------------------------------------------
// Gram + norms (unchanged).
__global__ __launch_bounds__(256) void dots_kernel(const float* __restrict__ xg) {
    __shared__ float qs[16][260];
    __shared__ float ks[16][260];
    __shared__ float s_nq[16], s_nk[16];

    int tid = threadIdx.x;
    int bh  = blockIdx.x >> 5;
    int sl  = blockIdx.x & 31;
    int b   = bh >> 2, hh = bh & 3;
    int i = tid >> 4, j = tid & 15;
    int s0 = sl * 2048;

    if (tid < 16) { s_nq[tid] = 0.f; s_nk[tid] = 0.f; }

    float g = 0.f, nqp = 0.f, nkp = 0.f;
    for (int ch = 0; ch < 8; ++ch) {
        __syncthreads();
        int sbase = s0 + ch*256;
        #pragma unroll
        for (int e = 0; e < 8; ++e) {
            int lin = tid + e*256;
            int r = lin >> 6, c4 = lin & 63;
            const float* src = (r < 16)
                ? (xg     + (b*C + hh*HD + r)*S)
                : (g_conv + (b*C + hh*HD + (r-16))*S);
            float4 val = *(const float4*)(src + sbase + c4*4);
            float* dst = (r < 16) ? &qs[r][c4*4] : &ks[r-16][c4*4];
            dst[0] = val.x; dst[1] = val.y; dst[2] = val.z; dst[3] = val.w;
        }
        __syncthreads();
        #pragma unroll 8
        for (int s = 0; s < 256; s += 4) {
            float4 qv = *(const float4*)&qs[i][s];
            float4 kv = *(const float4*)&ks[j][s];
            g += qv.x*kv.x; g += qv.y*kv.y; g += qv.z*kv.z; g += qv.w*kv.w;
        }
        #pragma unroll 4
        for (int s = j; s < 256; s += 16) { float q0 = qs[i][s]; nqp += q0*q0; }
        #pragma unroll 4
        for (int s = i; s < 256; s += 16) { float k0 = ks[j][s]; nkp += k0*k0; }
    }
    atomicAdd(&g_gram[bh*256 + i*16 + j], g);
    atomicAdd(&s_nq[i], nqp);
    atomicAdd(&s_nk[j], nkp);
    __syncthreads();
    if (tid < 16)       atomicAdd(&g_qn2[bh*16 + tid], s_nq[tid]);
    else if (tid < 32)  atomicAdd(&g_kn2[bh*16 + tid-16], s_nk[tid-16]);
}

// ---------------------------------------------------------------------------
// Fused softmax + out (R3 config: launch_bounds(256,2), 29us).
__global__ __launch_bounds__(256, 2) void out_kernel(float* __restrict__ out,
                                                     const float* __restrict__ temp) {
    __shared__ float s_attn[16][16];
    int tid = threadIdx.x;
    int bh  = blockIdx.x >> 6;
    int tile = blockIdx.x & 63;
    int b = bh >> 2, hh = bh & 3;

    {
        int i = tid >> 4, j = tid & 15;
        float dq = fmaxf(sqrtf(g_qn2[bh*16 + i]), 1e-12f);
        float dk = fmaxf(sqrtf(g_kn2[bh*16 + j]), 1e-12f);
        float T  = temp[hh];
        float l  = g_gram[bh*256 + i*16 + j] / (dq*dk) * T;
        float m = l;
        #pragma unroll
        for (int off = 8; off > 0; off >>= 1)
            m = fmaxf(m, __shfl_xor_sync(0xffffffffu, m, off, 16));
        float e = expf(l - m);
        float ssum = e;
        #pragma unroll
        for (int off = 8; off > 0; off >>= 1)
            ssum += __shfl_xor_sync(0xffffffffu, ssum, off, 16);
        s_attn[i][j] = e / ssum;
    }
    __syncthreads();

    int s = tile*1024 + tid*4;
    float4 acc[16];
    #pragma unroll
    for (int o = 0; o < 16; o++) acc[o] = make_float4(0.f, 0.f, 0.f, 0.f);

    #pragma unroll
    for (int d = 0; d < 16; d++) {
        float4 kvv = *(const float4*)&g_conv[(b*C + hh*HD + d)*S + s];
        #pragma unroll
        for (int o = 0; o < 16; o++) {
            float a = s_attn[o][d];
            acc[o].x += a*kvv.x; acc[o].y += a*kvv.y;
            acc[o].z += a*kvv.z; acc[o].w += a*kvv.w;
        }
    }
    #pragma unroll
    for (int o = 0; o < 16; o++)
        *(float4*)&out[(b*C + hh*HD + o)*S + s] = acc[o];
}

// ---------------------------------------------------------------------------
extern "C" void kernel_launch(void* const* d_in, const int* in_sizes, int n_in,
                              void* d_out, int out_size) {
    const float* clone  = (const float*)d_in[0];
    const float* xg     = (const float*)d_in[1];
    const float* u      = (const float*)d_in[2];
    const float* v      = (const float*)d_in[3];
    const float* weight = (const float*)d_in[4];
    const float* temp   = (const float*)d_in[5];
    float* out = (float*)d_out;

    prep_kernel<<<16, 256>>>(weight);
    winograd_in<<<Bn*64*NT, 128>>>(clone);
    winograd_gemm<<<Bn*16*NBLK, 256>>>();
    winograd_out<<<Bn*64*NT, 128>>>();
    resample_kernel<<<Bn*S/256, 256>>>(u, v);
    dots_kernel<<<Bn*HEADS*32, 256>>>(xg);
    out_kernel<<<Bn*HEADS*64, 256>>>(out, temp);
}

// round 7
// speedup vs baseline: 2.6528x; 1.3544x over previous
#include <cuda_runtime.h>
#include <math.h>
#include <stdint.h>

#define Bn 2
#define C 64
#define H 256
#define W 256
#define S (H*W)
#define HEADS 4
#define HD 16

#define NT4 65           // F(4x4) tiles per dim (cover 260 >= 258 ext grid)
#define NTT4 (NT4*NT4)   // 4225 tiles
#define TS4 4352         // tile stride (34*128)
#define NBLK4 34         // gemm 128-tile blocks per (b,f)
#define NF 36            // frequencies
#define GRV 258          // valid ext-grid rows/cols
#define GP4 260          // winG stride (row & alloc)

// Scratch (device globals -- no allocations allowed; zero-initialized)
__device__ float g_conv[Bn*C*S];
__device__ float g_gram[Bn*HEADS*HD*HD];
__device__ float g_qn2[Bn*HEADS*HD];
__device__ float g_kn2[Bn*HEADS*HD];
__device__ __align__(16) float g_U[NF*64*64];        // [f][ci][co]
__device__ __align__(16) float g_V[Bn*NF*64*TS4];    // [b][f][ci][t]  ~80MB
__device__ __align__(16) float g_M[Bn*NF*64*TS4];    // [b][f][co][t]  ~80MB
__device__ __align__(16) float g_winG[Bn*64*GP4*GP4];

// ---------------------------------------------------------------------------
// B^T (F(4,3)) applied to 6-vector.
__device__ __forceinline__ void bt6(const float d0, const float d1, const float d2,
                                    const float d3, const float d4, const float d5,
                                    float* t) {
    t[0] = 4.f*d0 - 5.f*d2 + d4;
    t[1] = -4.f*d1 - 4.f*d2 + d3 + d4;
    t[2] =  4.f*d1 - 4.f*d2 - d3 + d4;
    t[3] = -2.f*d1 - d2 + 2.f*d3 + d4;
    t[4] =  2.f*d1 - d2 - 2.f*d3 + d4;
    t[5] =  4.f*d1 - 5.f*d3 + d5;
}

// ---------------------------------------------------------------------------
// Prep: U = G g G^T (6x6 per (ci,co)); zero gram accumulators.
__global__ void prep_kernel(const float* __restrict__ weight) {
    int t = blockIdx.x*256 + threadIdx.x;        // 0..4095
    if (t < 4096) {
        int co = t & 63, ci = t >> 6;
        float g[3][3];
        #pragma unroll
        for (int k = 0; k < 9; k++) g[k/3][k%3] = weight[(co*C + ci)*9 + k];
        float q[6][3];
        #pragma unroll
        for (int c = 0; c < 3; c++) {
            float g0 = g[0][c], g1 = g[1][c], g2 = g[2][c];
            q[0][c] = 0.25f*g0;
            q[1][c] = (-1.f/6.f)*(g0 + g1 + g2);
            q[2][c] = (-1.f/6.f)*(g0 - g1 + g2);
            q[3][c] = (1.f/24.f)*g0 + (1.f/12.f)*g1 + (1.f/6.f)*g2;
            q[4][c] = (1.f/24.f)*g0 - (1.f/12.f)*g1 + (1.f/6.f)*g2;
            q[5][c] = g2;
        }
        #pragma unroll
        for (int r = 0; r < 6; r++) {
            float g0 = q[r][0], g1 = q[r][1], g2 = q[r][2];
            float ur[6];
            ur[0] = 0.25f*g0;
            ur[1] = (-1.f/6.f)*(g0 + g1 + g2);
            ur[2] = (-1.f/6.f)*(g0 - g1 + g2);
            ur[3] = (1.f/24.f)*g0 + (1.f/12.f)*g1 + (1.f/6.f)*g2;
            ur[4] = (1.f/24.f)*g0 - (1.f/12.f)*g1 + (1.f/6.f)*g2;
            ur[5] = g2;
            #pragma unroll
            for (int c = 0; c < 6; c++)
                g_U[(r*6+c)*4096 + ci*64 + co] = ur[c];
        }
    }
    if (blockIdx.x == 0) {
        int tid = threadIdx.x;
        for (int k = tid; k < Bn*HEADS*HD*HD; k += 256) g_gram[k] = 0.f;
        for (int k = tid; k < Bn*HEADS*HD;    k += 256) { g_qn2[k] = 0.f; g_kn2[k] = 0.f; }
    }
}

// ---------------------------------------------------------------------------
// Input transform: V = B^T d B per 6x6 tile (stride 4, zero-padded clone).
__global__ __launch_bounds__(128) void winograd_in(const float* __restrict__ clone) {
    __shared__ float rows[6][256];
    int z  = blockIdx.x;
    int ty = z % NT4;
    int bc = z / NT4;                // b*64 + ci
    int ci = bc & 63, b = bc >> 6;
    int tid = threadIdx.x;

    const float* plane = clone + ((size_t)bc << 16);
    #pragma unroll
    for (int i = 0; i < 3; i++) {
        int idx = tid + i*128;               // 0..383: (row, float4-col)
        int r = idx >> 6, c4 = idx & 63;
        int gr = 4*ty - 2 + r;
        float4 val = make_float4(0.f,0.f,0.f,0.f);
        if ((unsigned)gr < 256u) val = *(const float4*)(plane + gr*256 + c4*4);
        *(float4*)&rows[r][c4*4] = val;
    }
    __syncthreads();

    int tx = tid;
    if (tx < NT4) {
        float d[6][6];
        int cbase = 4*tx - 2;
        #pragma unroll
        for (int jj = 0; jj < 6; jj++) {
            int cc = cbase + jj;
            bool ok = ((unsigned)cc < 256u);
            #pragma unroll
            for (int r = 0; r < 6; r++) d[r][jj] = ok ? rows[r][cc] : 0.f;
        }
        float t[6][6];
        #pragma unroll
        for (int c2 = 0; c2 < 6; c2++) {
            float tc[6];
            bt6(d[0][c2], d[1][c2], d[2][c2], d[3][c2], d[4][c2], d[5][c2], tc);
            #pragma unroll
            for (int r = 0; r < 6; r++) t[r][c2] = tc[r];
        }
        int tlin = ty*NT4 + tx;
        #pragma unroll
        for (int r = 0; r < 6; r++) {
            float vr[6];
            bt6(t[r][0], t[r][1], t[r][2], t[r][3], t[r][4], t[r][5], vr);
            #pragma unroll
            for (int c2 = 0; c2 < 6; c2++)
                g_V[((b*NF + r*6+c2)*64 + ci)*TS4 + tlin] = vr[c2];
        }
    }
}

// ---------------------------------------------------------------------------
// Per-frequency GEMM: M[bf][co][t] = sum_ci U[f][ci][co] * V[bf][ci][t].
// Block: 64 co x 128 t; thread: 4 co x 8 t.
__global__ __launch_bounds__(256) void winograd_gemm() {
    __shared__ float4 Vc[16][32];    // [ci_local][128 floats]
    __shared__ float4 Uc[16][16];    // [ci_local][64 floats]
    int bf = blockIdx.x / NBLK4;     // b*36 + f
    int tc = blockIdx.x % NBLK4;
    int f  = bf % NF;
    int t0 = tc * 128;
    int tid = threadIdx.x;
    int cg = tid >> 4, tg = tid & 15;

    float acc[4][8];
    #pragma unroll
    for (int i = 0; i < 4; i++)
        #pragma unroll
        for (int j = 0; j < 8; j++) acc[i][j] = 0.f;

    for (int ci0 = 0; ci0 < 64; ci0 += 16) {
        __syncthreads();
        {
            int r = tid >> 4, c = tid & 15;
            const float* vsrc = &g_V[(bf*64 + ci0 + r)*TS4 + t0];
            Vc[r][c]      = *(const float4*)(vsrc + c*4);
            Vc[r][c + 16] = *(const float4*)(vsrc + 64 + c*4);
            Uc[r][c]      = *(const float4*)&g_U[f*4096 + (ci0 + r)*64 + c*4];
        }
        __syncthreads();
        #pragma unroll
        for (int cl = 0; cl < 16; cl++) {
            float4 w  = Uc[cl][cg];
            float4 s0 = Vc[cl][tg*2];
            float4 s1 = Vc[cl][tg*2 + 1];
            acc[0][0] += w.x*s0.x; acc[0][1] += w.x*s0.y; acc[0][2] += w.x*s0.z; acc[0][3] += w.x*s0.w;
            acc[0][4] += w.x*s1.x; acc[0][5] += w.x*s1.y; acc[0][6] += w.x*s1.z; acc[0][7] += w.x*s1.w;
            acc[1][0] += w.y*s0.x; acc[1][1] += w.y*s0.y; acc[1][2] += w.y*s0.z; acc[1][3] += w.y*s0.w;
            acc[1][4] += w.y*s1.x; acc[1][5] += w.y*s1.y; acc[1][6] += w.y*s1.z; acc[1][7] += w.y*s1.w;
            acc[2][0] += w.z*s0.x; acc[2][1] += w.z*s0.y; acc[2][2] += w.z*s0.z; acc[2][3] += w.z*s0.w;
            acc[2][4] += w.z*s1.x; acc[2][5] += w.z*s1.y; acc[2][6] += w.z*s1.z; acc[2][7] += w.z*s1.w;
            acc[3][0] += w.w*s0.x; acc[3][1] += w.w*s0.y; acc[3][2] += w.w*s0.z; acc[3][3] += w.w*s0.w;
            acc[3][4] += w.w*s1.x; acc[3][5] += w.w*s1.y; acc[3][6] += w.w*s1.z; acc[3][7] += w.w*s1.w;
        }
    }
    #pragma unroll
    for (int i = 0; i < 4; i++) {
        float* mp = &g_M[(bf*64 + cg*4 + i)*TS4 + t0 + tg*8];
        *(float4*)mp       = make_float4(acc[i][0], acc[i][1], acc[i][2], acc[i][3]);
        *(float4*)(mp + 4) = make_float4(acc[i][4], acc[i][5], acc[i][6], acc[i][7]);
    }
}

// ---------------------------------------------------------------------------
// Output transform: Y = A^T m A (4x4 outputs) -> dense conv on extended grid.
__global__ __launch_bounds__(128) void winograd_out() {
    int z  = blockIdx.x;
    int ty = z % NT4;
    int bc = z / NT4;                // b*64 + co
    int tid = threadIdx.x;
    int b = bc >> 6;

    int tx = tid;
    if (tx >= NT4) return;
    int tlin = ty*NT4 + tx;
    float m[6][6];
    #pragma unroll
    for (int f = 0; f < NF; f++)
        m[f/6][f%6] = g_M[((b*NF + f)*64 + (bc & 63))*TS4 + tlin];

    float t2[4][6];
    #pragma unroll
    for (int c2 = 0; c2 < 6; c2++) {
        float m0 = m[0][c2], m1 = m[1][c2], m2 = m[2][c2];
        float m3 = m[3][c2], m4 = m[4][c2], m5 = m[5][c2];
        t2[0][c2] = m0 + m1 + m2 + m3 + m4;
        t2[1][c2] = m1 - m2 + 2.f*(m3 - m4);
        t2[2][c2] = m1 + m2 + 4.f*(m3 + m4);
        t2[3][c2] = m1 - m2 + 8.f*(m3 - m4) + m5;
    }
    float* gbase = &g_winG[((size_t)bc*GP4 + 4*ty)*GP4 + 4*tx];
    #pragma unroll
    for (int r = 0; r < 4; r++) {
        float a0 = t2[r][0], a1 = t2[r][1], a2 = t2[r][2];
        float a3 = t2[r][3], a4 = t2[r][4], a5 = t2[r][5];
        float y0 = a0 + a1 + a2 + a3 + a4;
        float y1 = a1 - a2 + 2.f*(a3 - a4);
        float y2 = a1 + a2 + 4.f*(a3 + a4);
        float y3 = a1 - a2 + 8.f*(a3 - a4) + a5;
        *(float4*)(gbase + r*GP4) = make_float4(y0, y1, y2, y3);
    }
}

// ---------------------------------------------------------------------------
// Flow-guided bilinear resample of G -> deform conv output.
__global__ __launch_bounds__(256) void resample_kernel(
    const float* __restrict__ u, const float* __restrict__ v)
{
    int idx = blockIdx.x*256 + threadIdx.x;
    int b = idx >> 16, p = idx & 65535;
    int y = p >> 8, x = p & 255;
    float py  = (float)y + v[b*S + p];
    float px_ = (float)x + u[b*S + p];
    float fy = floorf(py), fx = floorf(px_);
    int y0 = (int)fy, x0 = (int)fx;
    float wy = py - fy, wx = px_ - fx;
    bool r0 = ((unsigned)(y0+1) < (unsigned)GRV);
    bool r1 = ((unsigned)(y0+2) < (unsigned)GRV);
    bool c0 = ((unsigned)(x0+1) < (unsigned)GRV);
    bool c1 = ((unsigned)(x0+2) < (unsigned)GRV);
    int off = (y0+1)*GP4 + (x0+1);
    float w00 = (1.f-wy)*(1.f-wx), w01 = (1.f-wy)*wx;
    float w10 = wy*(1.f-wx),       w11 = wy*wx;

    const float* Gb = g_winG + (size_t)(b*64)*GP4*GP4;
    float* dst = &g_conv[(size_t)(b*64)*S + p];
    #pragma unroll 4
    for (int ch = 0; ch < 64; ch++) {
        const float* Gp = Gb + (size_t)ch*GP4*GP4;
        float g00 = (r0 && c0) ? __ldg(Gp + off)         : 0.f;
        float g01 = (r0 && c1) ? __ldg(Gp + off + 1)     : 0.f;
        float g10 = (r1 && c0) ? __ldg(Gp + off + GP4)   : 0.f;
        float g11 = (r1 && c1) ? __ldg(Gp + off + GP4+1) : 0.f;
        dst[(size_t)ch*S] = w00*g00 + w01*g01 + w10*g10 + w11*g11;
    }
}

// ---------------------------------------------------------------------------
// Gram + norms (unchanged).
__global__ __launch_bounds__(256) void dots_kernel(const float* __restrict__ xg) {
    __shared__ float qs[16][260];
    __shared__ float ks[16][260];
    __shared__ float s_nq[16], s_nk[16];

    int tid = threadIdx.x;
    int bh  = blockIdx.x >> 5;
    int sl  = blockIdx.x & 31;
    int b   = bh >> 2, hh = bh & 3;
    int i = tid >> 4, j = tid & 15;
    int s0 = sl * 2048;

    if (tid < 16) { s_nq[tid] = 0.f; s_nk[tid] = 0.f; }

    float g = 0.f, nqp = 0.f, nkp = 0.f;
    for (int ch = 0; ch < 8; ++ch) {
        __syncthreads();
        int sbase = s0 + ch*256;
        #pragma unroll
        for (int e = 0; e < 8; ++e) {
            int lin = tid + e*256;
            int r = lin >> 6, c4 = lin & 63;
            const float* src = (r < 16)
                ? (xg     + (b*C + hh*HD + r)*S)
                : (g_conv + (b*C + hh*HD + (r-16))*S);
            float4 val = *(const float4*)(src + sbase + c4*4);
            float* dst = (r < 16) ? &qs[r][c4*4] : &ks[r-16][c4*4];
            dst[0] = val.x; dst[1] = val.y; dst[2] = val.z; dst[3] = val.w;
        }
        __syncthreads();
        #pragma unroll 8
        for (int s = 0; s < 256; s += 4) {
            float4 qv = *(const float4*)&qs[i][s];
            float4 kv = *(const float4*)&ks[j][s];
            g += qv.x*kv.x; g += qv.y*kv.y; g += qv.z*kv.z; g += qv.w*kv.w;
        }
        #pragma unroll 4
        for (int s = j; s < 256; s += 16) { float q0 = qs[i][s]; nqp += q0*q0; }
        #pragma unroll 4
        for (int s = i; s < 256; s += 16) { float k0 = ks[j][s]; nkp += k0*k0; }
    }
    atomicAdd(&g_gram[bh*256 + i*16 + j], g);
    atomicAdd(&s_nq[i], nqp);
    atomicAdd(&s_nk[j], nkp);
    __syncthreads();
    if (tid < 16)       atomicAdd(&g_qn2[bh*16 + tid], s_nq[tid]);
    else if (tid < 32)  atomicAdd(&g_kn2[bh*16 + tid-16], s_nk[tid-16]);
}

// ---------------------------------------------------------------------------
// Fused softmax + out.
__global__ __launch_bounds__(256, 2) void out_kernel(float* __restrict__ out,
                                                     const float* __restrict__ temp) {
    __shared__ float s_attn[16][16];
    int tid = threadIdx.x;
    int bh  = blockIdx.x >> 6;
    int tile = blockIdx.x & 63;
    int b = bh >> 2, hh = bh & 3;

    {
        int i = tid >> 4, j = tid & 15;
        float dq = fmaxf(sqrtf(g_qn2[bh*16 + i]), 1e-12f);
        float dk = fmaxf(sqrtf(g_kn2[bh*16 + j]), 1e-12f);
        float T  = temp[hh];
        float l  = g_gram[bh*256 + i*16 + j] / (dq*dk) * T;
        float m = l;
        #pragma unroll
        for (int off = 8; off > 0; off >>= 1)
            m = fmaxf(m, __shfl_xor_sync(0xffffffffu, m, off, 16));
        float e = expf(l - m);
        float ssum = e;
        #pragma unroll
        for (int off = 8; off > 0; off >>= 1)
            ssum += __shfl_xor_sync(0xffffffffu, ssum, off, 16);
        s_attn[i][j] = e / ssum;
    }
    __syncthreads();

    int s = tile*1024 + tid*4;
    float4 acc[16];
    #pragma unroll
    for (int o = 0; o < 16; o++) acc[o] = make_float4(0.f, 0.f, 0.f, 0.f);

    #pragma unroll
    for (int d = 0; d < 16; d++) {
        float4 kvv = *(const float4*)&g_conv[(b*C + hh*HD + d)*S + s];
        #pragma unroll
        for (int o = 0; o < 16; o++) {
            float a = s_attn[o][d];
            acc[o].x += a*kvv.x; acc[o].y += a*kvv.y;
            acc[o].z += a*kvv.z; acc[o].w += a*kvv.w;
        }
    }
    #pragma unroll
    for (int o = 0; o < 16; o++)
        *(float4*)&out[(b*C + hh*HD + o)*S + s] = acc[o];
}

// ---------------------------------------------------------------------------
extern "C" void kernel_launch(void* const* d_in, const int* in_sizes, int n_in,
                              void* d_out, int out_size) {
    const float* clone  = (const float*)d_in[0];
    const float* xg     = (const float*)d_in[1];
    const float* u      = (const float*)d_in[2];
    const float* v      = (const float*)d_in[3];
    const float* weight = (const float*)d_in[4];
    const float* temp   = (const float*)d_in[5];
    float* out = (float*)d_out;

    prep_kernel<<<16, 256>>>(weight);
    winograd_in<<<Bn*64*NT4, 128>>>(clone);
    winograd_gemm<<<Bn*NF*NBLK4, 256>>>();
    winograd_out<<<Bn*64*NT4, 128>>>();
    resample_kernel<<<Bn*S/256, 256>>>(u, v);
    dots_kernel<<<Bn*HEADS*32, 256>>>(xg);
    out_kernel<<<Bn*HEADS*64, 256>>>(out, temp);
}

// round 8
// speedup vs baseline: 2.6668x; 1.0053x over previous
#include <cuda_runtime.h>
#include <math.h>
#include <stdint.h>

#define Bn 2
#define C 64
#define H 256
#define W 256
#define S (H*W)
#define HEADS 4
#define HD 16

#define NT4 65           // F(4x4) tiles per dim (cover 260 >= 258 ext grid)
#define NTT4 (NT4*NT4)   // 4225 tiles
#define TS4 4352         // tile stride (34*128)
#define NBLK4 34         // gemm 128-tile blocks per (b,f)
#define NF 36            // frequencies
#define GRV 258          // valid ext-grid rows/cols
#define GP4 260          // winG stride (row & alloc)

typedef unsigned long long ull;

// Scratch (device globals -- no allocations allowed; zero-initialized)
__device__ float g_conv[Bn*C*S];
__device__ float g_gram[Bn*HEADS*HD*HD];
__device__ float g_qn2[Bn*HEADS*HD];
__device__ float g_kn2[Bn*HEADS*HD];
__device__ __align__(16) float g_U[NF*64*64];        // [f][ci][co]
__device__ __align__(16) float g_V[Bn*NF*64*TS4];    // [b][f][ci][t]  ~80MB
__device__ __align__(16) float g_M[Bn*NF*64*TS4];    // [b][f][co][t]  ~80MB
__device__ __align__(16) float g_winG[Bn*64*GP4*GP4];

__device__ __forceinline__ void fma2(ull& d, ull a, ull b) {
    asm("fma.rn.f32x2 %0, %1, %2, %0;" : "+l"(d) : "l"(a), "l"(b));
}
__device__ __forceinline__ ull splat2(float w) {
    ull r; asm("mov.b64 %0, {%1, %1};" : "=l"(r) : "f"(w)); return r;
}
__device__ __forceinline__ float2 unpack2(ull a) {
    float2 f; asm("mov.b64 {%0,%1}, %2;" : "=f"(f.x), "=f"(f.y) : "l"(a)); return f;
}

// ---------------------------------------------------------------------------
// B^T (F(4,3)) applied to 6-vector.
__device__ __forceinline__ void bt6(const float d0, const float d1, const float d2,
                                    const float d3, const float d4, const float d5,
                                    float* t) {
    t[0] = 4.f*d0 - 5.f*d2 + d4;
    t[1] = -4.f*d1 - 4.f*d2 + d3 + d4;
    t[2] =  4.f*d1 - 4.f*d2 - d3 + d4;
    t[3] = -2.f*d1 - d2 + 2.f*d3 + d4;
    t[4] =  2.f*d1 - d2 - 2.f*d3 + d4;
    t[5] =  4.f*d1 - 5.f*d3 + d5;
}

// ---------------------------------------------------------------------------
// Prep: U = G g G^T (6x6 per (ci,co)); zero gram accumulators.
__global__ void prep_kernel(const float* __restrict__ weight) {
    int t = blockIdx.x*256 + threadIdx.x;        // 0..4095
    if (t < 4096) {
        int co = t & 63, ci = t >> 6;
        float g[3][3];
        #pragma unroll
        for (int k = 0; k < 9; k++) g[k/3][k%3] = weight[(co*C + ci)*9 + k];
        float q[6][3];
        #pragma unroll
        for (int c = 0; c < 3; c++) {
            float g0 = g[0][c], g1 = g[1][c], g2 = g[2][c];
            q[0][c] = 0.25f*g0;
            q[1][c] = (-1.f/6.f)*(g0 + g1 + g2);
            q[2][c] = (-1.f/6.f)*(g0 - g1 + g2);
            q[3][c] = (1.f/24.f)*g0 + (1.f/12.f)*g1 + (1.f/6.f)*g2;
            q[4][c] = (1.f/24.f)*g0 - (1.f/12.f)*g1 + (1.f/6.f)*g2;
            q[5][c] = g2;
        }
        #pragma unroll
        for (int r = 0; r < 6; r++) {
            float g0 = q[r][0], g1 = q[r][1], g2 = q[r][2];
            float ur[6];
            ur[0] = 0.25f*g0;
            ur[1] = (-1.f/6.f)*(g0 + g1 + g2);
            ur[2] = (-1.f/6.f)*(g0 - g1 + g2);
            ur[3] = (1.f/24.f)*g0 + (1.f/12.f)*g1 + (1.f/6.f)*g2;
            ur[4] = (1.f/24.f)*g0 - (1.f/12.f)*g1 + (1.f/6.f)*g2;
            ur[5] = g2;
            #pragma unroll
            for (int c = 0; c < 6; c++)
                g_U[(r*6+c)*4096 + ci*64 + co] = ur[c];
        }
    }
    if (blockIdx.x == 0) {
        int tid = threadIdx.x;
        for (int k = tid; k < Bn*HEADS*HD*HD; k += 256) g_gram[k] = 0.f;
        for (int k = tid; k < Bn*HEADS*HD;    k += 256) { g_qn2[k] = 0.f; g_kn2[k] = 0.f; }
    }
}

// ---------------------------------------------------------------------------
// Input transform: V = B^T d B per 6x6 tile (stride 4, zero-padded clone).
__global__ __launch_bounds__(128) void winograd_in(const float* __restrict__ clone) {
    __shared__ float rows[6][256];
    int z  = blockIdx.x;
    int ty = z % NT4;
    int bc = z / NT4;                // b*64 + ci
    int ci = bc & 63, b = bc >> 6;
    int tid = threadIdx.x;

    const float* plane = clone + ((size_t)bc << 16);
    #pragma unroll
    for (int i = 0; i < 3; i++) {
        int idx = tid + i*128;               // 0..383: (row, float4-col)
        int r = idx >> 6, c4 = idx & 63;
        int gr = 4*ty - 2 + r;
        float4 val = make_float4(0.f,0.f,0.f,0.f);
        if ((unsigned)gr < 256u) val = *(const float4*)(plane + gr*256 + c4*4);
        *(float4*)&rows[r][c4*4] = val;
    }
    __syncthreads();

    int tx = tid;
    if (tx < NT4) {
        float d[6][6];
        int cbase = 4*tx - 2;
        #pragma unroll
        for (int jj = 0; jj < 6; jj++) {
            int cc = cbase + jj;
            bool ok = ((unsigned)cc < 256u);
            #pragma unroll
            for (int r = 0; r < 6; r++) d[r][jj] = ok ? rows[r][cc] : 0.f;
        }
        float t[6][6];
        #pragma unroll
        for (int c2 = 0; c2 < 6; c2++) {
            float tc[6];
            bt6(d[0][c2], d[1][c2], d[2][c2], d[3][c2], d[4][c2], d[5][c2], tc);
            #pragma unroll
            for (int r = 0; r < 6; r++) t[r][c2] = tc[r];
        }
        int tlin = ty*NT4 + tx;
        #pragma unroll
        for (int r = 0; r < 6; r++) {
            float vr[6];
            bt6(t[r][0], t[r][1], t[r][2], t[r][3], t[r][4], t[r][5], vr);
            #pragma unroll
            for (int c2 = 0; c2 < 6; c2++)
                g_V[((b*NF + r*6+c2)*64 + ci)*TS4 + tlin] = vr[c2];
        }
    }
}

// ---------------------------------------------------------------------------
// Per-frequency GEMM, packed f32x2 mainloop:
//   M[bf][co][t] = sum_ci U[f][ci][co] * V[bf][ci][t].
// Block: 64 co x 128 t; thread: 4 co x 4 t-pairs (16 ull accumulators).
__global__ __launch_bounds__(256) void winograd_gemm() {
    __shared__ float4 Vc[16][32];    // [ci_local][128 floats]
    __shared__ float4 Uc[16][16];    // [ci_local][64 floats]
    int bf = blockIdx.x / NBLK4;     // b*36 + f
    int tc = blockIdx.x % NBLK4;
    int f  = bf % NF;
    int t0 = tc * 128;
    int tid = threadIdx.x;
    int cg = tid >> 4, tg = tid & 15;

    ull acc2[4][4];
    #pragma unroll
    for (int i = 0; i < 4; i++)
        #pragma unroll
        for (int j = 0; j < 4; j++) acc2[i][j] = 0ull;

    for (int ci0 = 0; ci0 < 64; ci0 += 16) {
        __syncthreads();
        {
            int r = tid >> 4, c = tid & 15;
            const float* vsrc = &g_V[(bf*64 + ci0 + r)*TS4 + t0];
            Vc[r][c]      = *(const float4*)(vsrc + c*4);
            Vc[r][c + 16] = *(const float4*)(vsrc + 64 + c*4);
            Uc[r][c]      = *(const float4*)&g_U[f*4096 + (ci0 + r)*64 + c*4];
        }
        __syncthreads();
        #pragma unroll
        for (int cl = 0; cl < 16; cl++) {
            float4 w = Uc[cl][cg];
            ull w0 = splat2(w.x), w1 = splat2(w.y), w2 = splat2(w.z), w3 = splat2(w.w);
            const ull* sp = (const ull*)&Vc[cl][tg*2];
            ull s0 = sp[0], s1 = sp[1], s2 = sp[2], s3 = sp[3];
            fma2(acc2[0][0], w0, s0); fma2(acc2[0][1], w0, s1);
            fma2(acc2[0][2], w0, s2); fma2(acc2[0][3], w0, s3);
            fma2(acc2[1][0], w1, s0); fma2(acc2[1][1], w1, s1);
            fma2(acc2[1][2], w1, s2); fma2(acc2[1][3], w1, s3);
            fma2(acc2[2][0], w2, s0); fma2(acc2[2][1], w2, s1);
            fma2(acc2[2][2], w2, s2); fma2(acc2[2][3], w2, s3);
            fma2(acc2[3][0], w3, s0); fma2(acc2[3][1], w3, s1);
            fma2(acc2[3][2], w3, s2); fma2(acc2[3][3], w3, s3);
        }
    }
    #pragma unroll
    for (int i = 0; i < 4; i++) {
        float2 f0 = unpack2(acc2[i][0]);
        float2 f1 = unpack2(acc2[i][1]);
        float2 f2 = unpack2(acc2[i][2]);
        float2 f3 = unpack2(acc2[i][3]);
        float* mp = &g_M[(bf*64 + cg*4 + i)*TS4 + t0 + tg*8];
        *(float4*)mp       = make_float4(f0.x, f0.y, f1.x, f1.y);
        *(float4*)(mp + 4) = make_float4(f2.x, f2.y, f3.x, f3.y);
    }
}

// ---------------------------------------------------------------------------
// Output transform: Y = A^T m A (4x4 outputs) -> dense conv on extended grid.
__global__ __launch_bounds__(128) void winograd_out() {
    int z  = blockIdx.x;
    int ty = z % NT4;
    int bc = z / NT4;                // b*64 + co
    int tid = threadIdx.x;
    int b = bc >> 6;

    int tx = tid;
    if (tx >= NT4) return;
    int tlin = ty*NT4 + tx;
    float m[6][6];
    #pragma unroll
    for (int f = 0; f < NF; f++)
        m[f/6][f%6] = g_M[((b*NF + f)*64 + (bc & 63))*TS4 + tlin];

    float t2[4][6];
    #pragma unroll
    for (int c2 = 0; c2 < 6; c2++) {
        float m0 = m[0][c2], m1 = m[1][c2], m2 = m[2][c2];
        float m3 = m[3][c2], m4 = m[4][c2], m5 = m[5][c2];
        t2[0][c2] = m0 + m1 + m2 + m3 + m4;
        t2[1][c2] = m1 - m2 + 2.f*(m3 - m4);
        t2[2][c2] = m1 + m2 + 4.f*(m3 + m4);
        t2[3][c2] = m1 - m2 + 8.f*(m3 - m4) + m5;
    }
    float* gbase = &g_winG[((size_t)bc*GP4 + 4*ty)*GP4 + 4*tx];
    #pragma unroll
    for (int r = 0; r < 4; r++) {
        float a0 = t2[r][0], a1 = t2[r][1], a2 = t2[r][2];
        float a3 = t2[r][3], a4 = t2[r][4], a5 = t2[r][5];
        float y0 = a0 + a1 + a2 + a3 + a4;
        float y1 = a1 - a2 + 2.f*(a3 - a4);
        float y2 = a1 + a2 + 4.f*(a3 + a4);
        float y3 = a1 - a2 + 8.f*(a3 - a4) + a5;
        *(float4*)(gbase + r*GP4) = make_float4(y0, y1, y2, y3);
    }
}

// ---------------------------------------------------------------------------
// Flow-guided bilinear resample of G -> deform conv output.
__global__ __launch_bounds__(256) void resample_kernel(
    const float* __restrict__ u, const float* __restrict__ v)
{
    int idx = blockIdx.x*256 + threadIdx.x;
    int b = idx >> 16, p = idx & 65535;
    int y = p >> 8, x = p & 255;
    float py  = (float)y + v[b*S + p];
    float px_ = (float)x + u[b*S + p];
    float fy = floorf(py), fx = floorf(px_);
    int y0 = (int)fy, x0 = (int)fx;
    float wy = py - fy, wx = px_ - fx;
    bool r0 = ((unsigned)(y0+1) < (unsigned)GRV);
    bool r1 = ((unsigned)(y0+2) < (unsigned)GRV);
    bool c0 = ((unsigned)(x0+1) < (unsigned)GRV);
    bool c1 = ((unsigned)(x0+2) < (unsigned)GRV);
    int off = (y0+1)*GP4 + (x0+1);
    float w00 = (1.f-wy)*(1.f-wx), w01 = (1.f-wy)*wx;
    float w10 = wy*(1.f-wx),       w11 = wy*wx;

    const float* Gb = g_winG + (size_t)(b*64)*GP4*GP4;
    float* dst = &g_conv[(size_t)(b*64)*S + p];
    #pragma unroll 4
    for (int ch = 0; ch < 64; ch++) {
        const float* Gp = Gb + (size_t)ch*GP4*GP4;
        float g00 = (r0 && c0) ? __ldg(Gp + off)         : 0.f;
        float g01 = (r0 && c1) ? __ldg(Gp + off + 1)     : 0.f;
        float g10 = (r1 && c0) ? __ldg(Gp + off + GP4)   : 0.f;
        float g11 = (r1 && c1) ? __ldg(Gp + off + GP4+1) : 0.f;
        dst[(size_t)ch*S] = w00*g00 + w01*g01 + w10*g10 + w11*g11;
    }
}

// ---------------------------------------------------------------------------
// Gram + norms (unchanged).
__global__ __launch_bounds__(256) void dots_kernel(const float* __restrict__ xg) {
    __shared__ float qs[16][260];
    __shared__ float ks[16][260];
    __shared__ float s_nq[16], s_nk[16];

    int tid = threadIdx.x;
    int bh  = blockIdx.x >> 5;
    int sl  = blockIdx.x & 31;
    int b   = bh >> 2, hh = bh & 3;
    int i = tid >> 4, j = tid & 15;
    int s0 = sl * 2048;

    if (tid < 16) { s_nq[tid] = 0.f; s_nk[tid] = 0.f; }

    float g = 0.f, nqp = 0.f, nkp = 0.f;
    for (int ch = 0; ch < 8; ++ch) {
        __syncthreads();
        int sbase = s0 + ch*256;
        #pragma unroll
        for (int e = 0; e < 8; ++e) {
            int lin = tid + e*256;
            int r = lin >> 6, c4 = lin & 63;
            const float* src = (r < 16)
                ? (xg     + (b*C + hh*HD + r)*S)
                : (g_conv + (b*C + hh*HD + (r-16))*S);
            float4 val = *(const float4*)(src + sbase + c4*4);
            float* dst = (r < 16) ? &qs[r][c4*4] : &ks[r-16][c4*4];
            dst[0] = val.x; dst[1] = val.y; dst[2] = val.z; dst[3] = val.w;
        }
        __syncthreads();
        #pragma unroll 8
        for (int s = 0; s < 256; s += 4) {
            float4 qv = *(const float4*)&qs[i][s];
            float4 kv = *(const float4*)&ks[j][s];
            g += qv.x*kv.x; g += qv.y*kv.y; g += qv.z*kv.z; g += qv.w*kv.w;
        }
        #pragma unroll 4
        for (int s = j; s < 256; s += 16) { float q0 = qs[i][s]; nqp += q0*q0; }
        #pragma unroll 4
        for (int s = i; s < 256; s += 16) { float k0 = ks[j][s]; nkp += k0*k0; }
    }
    atomicAdd(&g_gram[bh*256 + i*16 + j], g);
    atomicAdd(&s_nq[i], nqp);
    atomicAdd(&s_nk[j], nkp);
    __syncthreads();
    if (tid < 16)       atomicAdd(&g_qn2[bh*16 + tid], s_nq[tid]);
    else if (tid < 32)  atomicAdd(&g_kn2[bh*16 + tid-16], s_nk[tid-16]);
}

// ---------------------------------------------------------------------------
// Fused softmax + out.
__global__ __launch_bounds__(256, 2) void out_kernel(float* __restrict__ out,
                                                     const float* __restrict__ temp) {
    __shared__ float s_attn[16][16];
    int tid = threadIdx.x;
    int bh  = blockIdx.x >> 6;
    int tile = blockIdx.x & 63;
    int b = bh >> 2, hh = bh & 3;

    {
        int i = tid >> 4, j = tid & 15;
        float dq = fmaxf(sqrtf(g_qn2[bh*16 + i]), 1e-12f);
        float dk = fmaxf(sqrtf(g_kn2[bh*16 + j]), 1e-12f);
        float T  = temp[hh];
        float l  = g_gram[bh*256 + i*16 + j] / (dq*dk) * T;
        float m = l;
        #pragma unroll
        for (int off = 8; off > 0; off >>= 1)
            m = fmaxf(m, __shfl_xor_sync(0xffffffffu, m, off, 16));
        float e = expf(l - m);
        float ssum = e;
        #pragma unroll
        for (int off = 8; off > 0; off >>= 1)
            ssum += __shfl_xor_sync(0xffffffffu, ssum, off, 16);
        s_attn[i][j] = e / ssum;
    }
    __syncthreads();

    int s = tile*1024 + tid*4;
    float4 acc[16];
    #pragma unroll
    for (int o = 0; o < 16; o++) acc[o] = make_float4(0.f, 0.f, 0.f, 0.f);

    #pragma unroll
    for (int d = 0; d < 16; d++) {
        float4 kvv = *(const float4*)&g_conv[(b*C + hh*HD + d)*S + s];
        #pragma unroll
        for (int o = 0; o < 16; o++) {
            float a = s_attn[o][d];
            acc[o].x += a*kvv.x; acc[o].y += a*kvv.y;
            acc[o].z += a*kvv.z; acc[o].w += a*kvv.w;
        }
    }
    #pragma unroll
    for (int o = 0; o < 16; o++)
        *(float4*)&out[(b*C + hh*HD + o)*S + s] = acc[o];
}

// ---------------------------------------------------------------------------
extern "C" void kernel_launch(void* const* d_in, const int* in_sizes, int n_in,
                              void* d_out, int out_size) {
    const float* clone  = (const float*)d_in[0];
    const float* xg     = (const float*)d_in[1];
    const float* u      = (const float*)d_in[2];
    const float* v      = (const float*)d_in[3];
    const float* weight = (const float*)d_in[4];
    const float* temp   = (const float*)d_in[5];
    float* out = (float*)d_out;

    prep_kernel<<<16, 256>>>(weight);
    winograd_in<<<Bn*64*NT4, 128>>>(clone);
    winograd_gemm<<<Bn*NF*NBLK4, 256>>>();
    winograd_out<<<Bn*64*NT4, 128>>>();
    resample_kernel<<<Bn*S/256, 256>>>(u, v);
    dots_kernel<<<Bn*HEADS*32, 256>>>(xg);
    out_kernel<<<Bn*HEADS*64, 256>>>(out, temp);
}

// round 9
// speedup vs baseline: 2.7203x; 1.0200x over previous
#include <cuda_runtime.h>
#include <math.h>
#include <stdint.h>

#define Bn 2
#define C 64
#define H 256
#define W 256
#define S (H*W)
#define HEADS 4
#define HD 16

#define NT4 65           // F(4x4) tiles per dim (cover 260 >= 258 ext grid)
#define NTT4 (NT4*NT4)   // 4225 tiles
#define TS4 4352         // tile stride (34*128)
#define NBLK4 34         // gemm 128-tile blocks per (b,f)
#define NF 36            // frequencies
#define GRV 258          // valid ext-grid rows/cols
#define GP4 260          // winG stride (row & alloc)

// Scratch (device globals -- no allocations allowed; zero-initialized)
__device__ float g_conv[Bn*C*S];
__device__ float g_gram[Bn*HEADS*HD*HD];
__device__ float g_qn2[Bn*HEADS*HD];
__device__ float g_kn2[Bn*HEADS*HD];
__device__ __align__(16) float g_U[NF*64*64];        // [f][ci][co]
__device__ __align__(16) float g_V[Bn*NF*64*TS4];    // [b][f][ci][t]  ~80MB
__device__ __align__(16) float g_M[Bn*NF*64*TS4];    // [b][f][co][t]  ~80MB
__device__ __align__(16) float g_winG[Bn*64*GP4*GP4];

// ---------------------------------------------------------------------------
// B^T (F(4,3)) applied to 6-vector.
__device__ __forceinline__ void bt6(const float d0, const float d1, const float d2,
                                    const float d3, const float d4, const float d5,
                                    float* t) {
    t[0] = 4.f*d0 - 5.f*d2 + d4;
    t[1] = -4.f*d1 - 4.f*d2 + d3 + d4;
    t[2] =  4.f*d1 - 4.f*d2 - d3 + d4;
    t[3] = -2.f*d1 - d2 + 2.f*d3 + d4;
    t[4] =  2.f*d1 - d2 - 2.f*d3 + d4;
    t[5] =  4.f*d1 - 5.f*d3 + d5;
}

// ---------------------------------------------------------------------------
// Prep: U = G g G^T (6x6 per (ci,co)); zero gram accumulators.
__global__ void prep_kernel(const float* __restrict__ weight) {
    int t = blockIdx.x*256 + threadIdx.x;        // 0..4095
    if (t < 4096) {
        int co = t & 63, ci = t >> 6;
        float g[3][3];
        #pragma unroll
        for (int k = 0; k < 9; k++) g[k/3][k%3] = weight[(co*C + ci)*9 + k];
        float q[6][3];
        #pragma unroll
        for (int c = 0; c < 3; c++) {
            float g0 = g[0][c], g1 = g[1][c], g2 = g[2][c];
            q[0][c] = 0.25f*g0;
            q[1][c] = (-1.f/6.f)*(g0 + g1 + g2);
            q[2][c] = (-1.f/6.f)*(g0 - g1 + g2);
            q[3][c] = (1.f/24.f)*g0 + (1.f/12.f)*g1 + (1.f/6.f)*g2;
            q[4][c] = (1.f/24.f)*g0 - (1.f/12.f)*g1 + (1.f/6.f)*g2;
            q[5][c] = g2;
        }
        #pragma unroll
        for (int r = 0; r < 6; r++) {
            float g0 = q[r][0], g1 = q[r][1], g2 = q[r][2];
            float ur[6];
            ur[0] = 0.25f*g0;
            ur[1] = (-1.f/6.f)*(g0 + g1 + g2);
            ur[2] = (-1.f/6.f)*(g0 - g1 + g2);
            ur[3] = (1.f/24.f)*g0 + (1.f/12.f)*g1 + (1.f/6.f)*g2;
            ur[4] = (1.f/24.f)*g0 - (1.f/12.f)*g1 + (1.f/6.f)*g2;
            ur[5] = g2;
            #pragma unroll
            for (int c = 0; c < 6; c++)
                g_U[(r*6+c)*4096 + ci*64 + co] = ur[c];
        }
    }
    if (blockIdx.x == 0) {
        int tid = threadIdx.x;
        for (int k = tid; k < Bn*HEADS*HD*HD; k += 256) g_gram[k] = 0.f;
        for (int k = tid; k < Bn*HEADS*HD;    k += 256) { g_qn2[k] = 0.f; g_kn2[k] = 0.f; }
    }
}

// ---------------------------------------------------------------------------
// Input transform: V = B^T d B per 6x6 tile (stride 4, zero-padded clone).
__global__ __launch_bounds__(128) void winograd_in(const float* __restrict__ clone) {
    __shared__ float rows[6][256];
    int z  = blockIdx.x;
    int ty = z % NT4;
    int bc = z / NT4;                // b*64 + ci
    int ci = bc & 63, b = bc >> 6;
    int tid = threadIdx.x;

    const float* plane = clone + ((size_t)bc << 16);
    #pragma unroll
    for (int i = 0; i < 3; i++) {
        int idx = tid + i*128;               // 0..383: (row, float4-col)
        int r = idx >> 6, c4 = idx & 63;
        int gr = 4*ty - 2 + r;
        float4 val = make_float4(0.f,0.f,0.f,0.f);
        if ((unsigned)gr < 256u) val = *(const float4*)(plane + gr*256 + c4*4);
        *(float4*)&rows[r][c4*4] = val;
    }
    __syncthreads();

    int tx = tid;
    if (tx < NT4) {
        float d[6][6];
        int cbase = 4*tx - 2;
        #pragma unroll
        for (int jj = 0; jj < 6; jj++) {
            int cc = cbase + jj;
            bool ok = ((unsigned)cc < 256u);
            #pragma unroll
            for (int r = 0; r < 6; r++) d[r][jj] = ok ? rows[r][cc] : 0.f;
        }
        float t[6][6];
        #pragma unroll
        for (int c2 = 0; c2 < 6; c2++) {
            float tc[6];
            bt6(d[0][c2], d[1][c2], d[2][c2], d[3][c2], d[4][c2], d[5][c2], tc);
            #pragma unroll
            for (int r = 0; r < 6; r++) t[r][c2] = tc[r];
        }
        int tlin = ty*NT4 + tx;
        #pragma unroll
        for (int r = 0; r < 6; r++) {
            float vr[6];
            bt6(t[r][0], t[r][1], t[r][2], t[r][3], t[r][4], t[r][5], vr);
            #pragma unroll
            for (int c2 = 0; c2 < 6; c2++)
                g_V[((b*NF + r*6+c2)*64 + ci)*TS4 + tlin] = vr[c2];
        }
    }
}

// ---------------------------------------------------------------------------
// Per-frequency GEMM, single-stage full-K smem:
//   M[bf][co][t] = sum_ci U[f][ci][co] * V[bf][ci][t].
// Block: 64 co x 128 t; stage Vs[64][128]+Us[64][64] (48KB), ONE sync,
// then 2048 uninterrupted FFMAs per thread (4 co x 8 t tile).
__global__ __launch_bounds__(256, 3) void winograd_gemm() {
    __shared__ float Vs[64][128];    // 32 KB
    __shared__ float Us[64][64];     // 16 KB
    int bf = blockIdx.x / NBLK4;     // b*36 + f
    int tc = blockIdx.x % NBLK4;
    int f  = bf % NF;
    int t0 = tc * 128;
    int tid = threadIdx.x;
    int cg = tid >> 4, tg = tid & 15;

    // ---- stage: whole K slab ----
    {
        const float* vsrc = &g_V[(size_t)(bf*64)*TS4 + t0];
        #pragma unroll
        for (int i = 0; i < 8; i++) {
            int lin = tid + i*256;           // 0..2047 float4 units
            int r = lin >> 5, c = lin & 31;
            *(float4*)&Vs[r][c*4] = *(const float4*)(vsrc + (size_t)r*TS4 + c*4);
        }
        const float* usrc = &g_U[f*4096];
        #pragma unroll
        for (int i = 0; i < 4; i++) {
            int lin = tid + i*256;           // 0..1023 float4 units
            int r = lin >> 4, c = lin & 15;
            *(float4*)&Us[r][c*4] = *(const float4*)(usrc + r*64 + c*4);
        }
    }
    __syncthreads();

    float acc[4][8];
    #pragma unroll
    for (int i = 0; i < 4; i++)
        #pragma unroll
        for (int j = 0; j < 8; j++) acc[i][j] = 0.f;

    #pragma unroll 8
    for (int cl = 0; cl < 64; cl++) {
        float4 w  = *(const float4*)&Us[cl][cg*4];
        float4 s0 = *(const float4*)&Vs[cl][tg*8];
        float4 s1 = *(const float4*)&Vs[cl][tg*8 + 4];
        acc[0][0] += w.x*s0.x; acc[0][1] += w.x*s0.y; acc[0][2] += w.x*s0.z; acc[0][3] += w.x*s0.w;
        acc[0][4] += w.x*s1.x; acc[0][5] += w.x*s1.y; acc[0][6] += w.x*s1.z; acc[0][7] += w.x*s1.w;
        acc[1][0] += w.y*s0.x; acc[1][1] += w.y*s0.y; acc[1][2] += w.y*s0.z; acc[1][3] += w.y*s0.w;
        acc[1][4] += w.y*s1.x; acc[1][5] += w.y*s1.y; acc[1][6] += w.y*s1.z; acc[1][7] += w.y*s1.w;
        acc[2][0] += w.z*s0.x; acc[2][1] += w.z*s0.y; acc[2][2] += w.z*s0.z; acc[2][3] += w.z*s0.w;
        acc[2][4] += w.z*s1.x; acc[2][5] += w.z*s1.y; acc[2][6] += w.z*s1.z; acc[2][7] += w.z*s1.w;
        acc[3][0] += w.w*s0.x; acc[3][1] += w.w*s0.y; acc[3][2] += w.w*s0.z; acc[3][3] += w.w*s0.w;
        acc[3][4] += w.w*s1.x; acc[3][5] += w.w*s1.y; acc[3][6] += w.w*s1.z; acc[3][7] += w.w*s1.w;
    }

    #pragma unroll
    for (int i = 0; i < 4; i++) {
        float* mp = &g_M[(size_t)(bf*64 + cg*4 + i)*TS4 + t0 + tg*8];
        *(float4*)mp       = make_float4(acc[i][0], acc[i][1], acc[i][2], acc[i][3]);
        *(float4*)(mp + 4) = make_float4(acc[i][4], acc[i][5], acc[i][6], acc[i][7]);
    }
}

// ---------------------------------------------------------------------------
// Output transform: Y = A^T m A (4x4 outputs) -> dense conv on extended grid.
__global__ __launch_bounds__(128) void winograd_out() {
    int z  = blockIdx.x;
    int ty = z % NT4;
    int bc = z / NT4;                // b*64 + co
    int tid = threadIdx.x;
    int b = bc >> 6;

    int tx = tid;
    if (tx >= NT4) return;
    int tlin = ty*NT4 + tx;
    float m[6][6];
    #pragma unroll
    for (int f = 0; f < NF; f++)
        m[f/6][f%6] = g_M[((b*NF + f)*64 + (bc & 63))*TS4 + tlin];

    float t2[4][6];
    #pragma unroll
    for (int c2 = 0; c2 < 6; c2++) {
        float m0 = m[0][c2], m1 = m[1][c2], m2 = m[2][c2];
        float m3 = m[3][c2], m4 = m[4][c2], m5 = m[5][c2];
        t2[0][c2] = m0 + m1 + m2 + m3 + m4;
        t2[1][c2] = m1 - m2 + 2.f*(m3 - m4);
        t2[2][c2] = m1 + m2 + 4.f*(m3 + m4);
        t2[3][c2] = m1 - m2 + 8.f*(m3 - m4) + m5;
    }
    float* gbase = &g_winG[((size_t)bc*GP4 + 4*ty)*GP4 + 4*tx];
    #pragma unroll
    for (int r = 0; r < 4; r++) {
        float a0 = t2[r][0], a1 = t2[r][1], a2 = t2[r][2];
        float a3 = t2[r][3], a4 = t2[r][4], a5 = t2[r][5];
        float y0 = a0 + a1 + a2 + a3 + a4;
        float y1 = a1 - a2 + 2.f*(a3 - a4);
        float y2 = a1 + a2 + 4.f*(a3 + a4);
        float y3 = a1 - a2 + 8.f*(a3 - a4) + a5;
        *(float4*)(gbase + r*GP4) = make_float4(y0, y1, y2, y3);
    }
}

// ---------------------------------------------------------------------------
// Flow-guided bilinear resample of G -> deform conv output.
__global__ __launch_bounds__(256) void resample_kernel(
    const float* __restrict__ u, const float* __restrict__ v)
{
    int idx = blockIdx.x*256 + threadIdx.x;
    int b = idx >> 16, p = idx & 65535;
    int y = p >> 8, x = p & 255;
    float py  = (float)y + v[b*S + p];
    float px_ = (float)x + u[b*S + p];
    float fy = floorf(py), fx = floorf(px_);
    int y0 = (int)fy, x0 = (int)fx;
    float wy = py - fy, wx = px_ - fx;
    bool r0 = ((unsigned)(y0+1) < (unsigned)GRV);
    bool r1 = ((unsigned)(y0+2) < (unsigned)GRV);
    bool c0 = ((unsigned)(x0+1) < (unsigned)GRV);
    bool c1 = ((unsigned)(x0+2) < (unsigned)GRV);
    int off = (y0+1)*GP4 + (x0+1);
    float w00 = (1.f-wy)*(1.f-wx), w01 = (1.f-wy)*wx;
    float w10 = wy*(1.f-wx),       w11 = wy*wx;

    const float* Gb = g_winG + (size_t)(b*64)*GP4*GP4;
    float* dst = &g_conv[(size_t)(b*64)*S + p];
    #pragma unroll 4
    for (int ch = 0; ch < 64; ch++) {
        const float* Gp = Gb + (size_t)ch*GP4*GP4;
        float g00 = (r0 && c0) ? __ldg(Gp + off)         : 0.f;
        float g01 = (r0 && c1) ? __ldg(Gp + off + 1)     : 0.f;
        float g10 = (r1 && c0) ? __ldg(Gp + off + GP4)   : 0.f;
        float g11 = (r1 && c1) ? __ldg(Gp + off + GP4+1) : 0.f;
        dst[(size_t)ch*S] = w00*g00 + w01*g01 + w10*g10 + w11*g11;
    }
}

// ---------------------------------------------------------------------------
// Gram + norms (unchanged).
__global__ __launch_bounds__(256) void dots_kernel(const float* __restrict__ xg) {
    __shared__ float qs[16][260];
    __shared__ float ks[16][260];
    __shared__ float s_nq[16], s_nk[16];

    int tid = threadIdx.x;
    int bh  = blockIdx.x >> 5;
    int sl  = blockIdx.x & 31;
    int b   = bh >> 2, hh = bh & 3;
    int i = tid >> 4, j = tid & 15;
    int s0 = sl * 2048;

    if (tid < 16) { s_nq[tid] = 0.f; s_nk[tid] = 0.f; }

    float g = 0.f, nqp = 0.f, nkp = 0.f;
    for (int ch = 0; ch < 8; ++ch) {
        __syncthreads();
        int sbase = s0 + ch*256;
        #pragma unroll
        for (int e = 0; e < 8; ++e) {
            int lin = tid + e*256;
            int r = lin >> 6, c4 = lin & 63;
            const float* src = (r < 16)
                ? (xg     + (b*C + hh*HD + r)*S)
                : (g_conv + (b*C + hh*HD + (r-16))*S);
            float4 val = *(const float4*)(src + sbase + c4*4);
            float* dst = (r < 16) ? &qs[r][c4*4] : &ks[r-16][c4*4];
            dst[0] = val.x; dst[1] = val.y; dst[2] = val.z; dst[3] = val.w;
        }
        __syncthreads();
        #pragma unroll 8
        for (int s = 0; s < 256; s += 4) {
            float4 qv = *(const float4*)&qs[i][s];
            float4 kv = *(const float4*)&ks[j][s];
            g += qv.x*kv.x; g += qv.y*kv.y; g += qv.z*kv.z; g += qv.w*kv.w;
        }
        #pragma unroll 4
        for (int s = j; s < 256; s += 16) { float q0 = qs[i][s]; nqp += q0*q0; }
        #pragma unroll 4
        for (int s = i; s < 256; s += 16) { float k0 = ks[j][s]; nkp += k0*k0; }
    }
    atomicAdd(&g_gram[bh*256 + i*16 + j], g);
    atomicAdd(&s_nq[i], nqp);
    atomicAdd(&s_nk[j], nkp);
    __syncthreads();
    if (tid < 16)       atomicAdd(&g_qn2[bh*16 + tid], s_nq[tid]);
    else if (tid < 32)  atomicAdd(&g_kn2[bh*16 + tid-16], s_nk[tid-16]);
}

// ---------------------------------------------------------------------------
// Fused softmax + out.
__global__ __launch_bounds__(256, 2) void out_kernel(float* __restrict__ out,
                                                     const float* __restrict__ temp) {
    __shared__ float s_attn[16][16];
    int tid = threadIdx.x;
    int bh  = blockIdx.x >> 6;
    int tile = blockIdx.x & 63;
    int b = bh >> 2, hh = bh & 3;

    {
        int i = tid >> 4, j = tid & 15;
        float dq = fmaxf(sqrtf(g_qn2[bh*16 + i]), 1e-12f);
        float dk = fmaxf(sqrtf(g_kn2[bh*16 + j]), 1e-12f);
        float T  = temp[hh];
        float l  = g_gram[bh*256 + i*16 + j] / (dq*dk) * T;
        float m = l;
        #pragma unroll
        for (int off = 8; off > 0; off >>= 1)
            m = fmaxf(m, __shfl_xor_sync(0xffffffffu, m, off, 16));
        float e = expf(l - m);
        float ssum = e;
        #pragma unroll
        for (int off = 8; off > 0; off >>= 1)
            ssum += __shfl_xor_sync(0xffffffffu, ssum, off, 16);
        s_attn[i][j] = e / ssum;
    }
    __syncthreads();

    int s = tile*1024 + tid*4;
    float4 acc[16];
    #pragma unroll
    for (int o = 0; o < 16; o++) acc[o] = make_float4(0.f, 0.f, 0.f, 0.f);

    #pragma unroll
    for (int d = 0; d < 16; d++) {
        float4 kvv = *(const float4*)&g_conv[(b*C + hh*HD + d)*S + s];
        #pragma unroll
        for (int o = 0; o < 16; o++) {
            float a = s_attn[o][d];
            acc[o].x += a*kvv.x; acc[o].y += a*kvv.y;
            acc[o].z += a*kvv.z; acc[o].w += a*kvv.w;
        }
    }
    #pragma unroll
    for (int o = 0; o < 16; o++)
        *(float4*)&out[(b*C + hh*HD + o)*S + s] = acc[o];
}

// ---------------------------------------------------------------------------
extern "C" void kernel_launch(void* const* d_in, const int* in_sizes, int n_in,
                              void* d_out, int out_size) {
    const float* clone  = (const float*)d_in[0];
    const float* xg     = (const float*)d_in[1];
    const float* u      = (const float*)d_in[2];
    const float* v      = (const float*)d_in[3];
    const float* weight = (const float*)d_in[4];
    const float* temp   = (const float*)d_in[5];
    float* out = (float*)d_out;

    prep_kernel<<<16, 256>>>(weight);
    winograd_in<<<Bn*64*NT4, 128>>>(clone);
    winograd_gemm<<<Bn*NF*NBLK4, 256>>>();
    winograd_out<<<Bn*64*NT4, 128>>>();
    resample_kernel<<<Bn*S/256, 256>>>(u, v);
    dots_kernel<<<Bn*HEADS*32, 256>>>(xg);
    out_kernel<<<Bn*HEADS*64, 256>>>(out, temp);
}

// round 11
// speedup vs baseline: 3.0355x; 1.1159x over previous
#include <cuda_runtime.h>
#include <math.h>
#include <stdint.h>

#define Bn 2
#define C 64
#define H 256
#define W 256
#define S (H*W)
#define HEADS 4
#define HD 16

#define NT4 65           // F(4x4) tiles per dim (cover 260 >= 258 ext grid)
#define NTT4 (NT4*NT4)   // 4225 tiles
#define TS4 4352         // tile stride (34*128)
#define NBLK4 34         // gemm 128-tile blocks per (b,f)
#define NF 36            // frequencies
#define GRV 258          // valid ext-grid rows/cols
#define GP4 260          // winG stride (row & alloc)
#define NTYG 17          // groups of 4 ty rows (covers 65... 17*4=68)

// Scratch (device globals -- no allocations allowed; zero-initialized)
__device__ float g_conv[Bn*C*S];
__device__ float g_gram[Bn*HEADS*HD*HD];
__device__ float g_qn2[Bn*HEADS*HD];
__device__ float g_kn2[Bn*HEADS*HD];
__device__ __align__(16) float g_U[NF*64*64];        // [f][ci][co]
__device__ __align__(16) float g_V[Bn*NF*64*TS4];    // [b][f][ci][t]  ~80MB
__device__ __align__(16) float g_M[Bn*NF*64*TS4];    // [b][f][co][t]  ~80MB
__device__ __align__(16) float g_winG[Bn*64*GP4*GP4];

// ---------------------------------------------------------------------------
// B^T (F(4,3)) applied to 6-vector.
__device__ __forceinline__ void bt6(const float d0, const float d1, const float d2,
                                    const float d3, const float d4, const float d5,
                                    float* t) {
    t[0] = 4.f*d0 - 5.f*d2 + d4;
    t[1] = -4.f*d1 - 4.f*d2 + d3 + d4;
    t[2] =  4.f*d1 - 4.f*d2 - d3 + d4;
    t[3] = -2.f*d1 - d2 + 2.f*d3 + d4;
    t[4] =  2.f*d1 - d2 - 2.f*d3 + d4;
    t[5] =  4.f*d1 - 5.f*d3 + d5;
}

// ---------------------------------------------------------------------------
// Prep: U = G g G^T (6x6 per (ci,co)); zero gram accumulators.
__global__ void prep_kernel(const float* __restrict__ weight) {
    int t = blockIdx.x*256 + threadIdx.x;        // 0..4095
    if (t < 4096) {
        int co = t & 63, ci = t >> 6;
        float g[3][3];
        #pragma unroll
        for (int k = 0; k < 9; k++) g[k/3][k%3] = weight[(co*C + ci)*9 + k];
        float q[6][3];
        #pragma unroll
        for (int c = 0; c < 3; c++) {
            float g0 = g[0][c], g1 = g[1][c], g2 = g[2][c];
            q[0][c] = 0.25f*g0;
            q[1][c] = (-1.f/6.f)*(g0 + g1 + g2);
            q[2][c] = (-1.f/6.f)*(g0 - g1 + g2);
            q[3][c] = (1.f/24.f)*g0 + (1.f/12.f)*g1 + (1.f/6.f)*g2;
            q[4][c] = (1.f/24.f)*g0 - (1.f/12.f)*g1 + (1.f/6.f)*g2;
            q[5][c] = g2;
        }
        #pragma unroll
        for (int r = 0; r < 6; r++) {
            float g0 = q[r][0], g1 = q[r][1], g2 = q[r][2];
            float ur[6];
            ur[0] = 0.25f*g0;
            ur[1] = (-1.f/6.f)*(g0 + g1 + g2);
            ur[2] = (-1.f/6.f)*(g0 - g1 + g2);
            ur[3] = (1.f/24.f)*g0 + (1.f/12.f)*g1 + (1.f/6.f)*g2;
            ur[4] = (1.f/24.f)*g0 - (1.f/12.f)*g1 + (1.f/6.f)*g2;
            ur[5] = g2;
            #pragma unroll
            for (int c = 0; c < 6; c++)
                g_U[(r*6+c)*4096 + ci*64 + co] = ur[c];
        }
    }
    if (blockIdx.x == 0) {
        int tid = threadIdx.x;
        for (int k = tid; k < Bn*HEADS*HD*HD; k += 256) g_gram[k] = 0.f;
        for (int k = tid; k < Bn*HEADS*HD;    k += 256) { g_qn2[k] = 0.f; g_kn2[k] = 0.f; }
    }
}

// ---------------------------------------------------------------------------
// Input transform: V = B^T d B per 6x6 tile (stride 4, zero-padded clone).
// Block = (b*64+ci)*NTYG + tyg; 4 ty rows x 65 tx tiles = 260 tasks over
// 256 threads via grid-stride loop (bugfix vs R10: last 4 tasks included).
__global__ __launch_bounds__(256) void winograd_in(const float* __restrict__ clone) {
    __shared__ float rows[18][256];
    int z   = blockIdx.x;
    int tyg = z % NTYG;
    int bc  = z / NTYG;              // b*64 + ci
    int ci  = bc & 63, b = bc >> 6;
    int tid = threadIdx.x;

    const float* plane = clone + ((size_t)bc << 16);
    int gr0 = 16*tyg - 2;
    for (int i = tid; i < 18*64; i += 256) {      // 1152 float4 loads
        int r = i >> 6, c4 = i & 63;
        int gr = gr0 + r;
        float4 val = make_float4(0.f,0.f,0.f,0.f);
        if ((unsigned)gr < 256u) val = *(const float4*)(plane + gr*256 + c4*4);
        *(float4*)&rows[r][c4*4] = val;
    }
    __syncthreads();

    for (int task = tid; task < 4*NT4; task += 256) {
        int tyl = task / NT4;            // 0..3
        int tx  = task - tyl*NT4;
        int ty  = 4*tyg + tyl;
        if (ty >= NT4) continue;
        float d[6][6];
        int cbase = 4*tx - 2;
        int rl = 4*tyl;
        #pragma unroll
        for (int jj = 0; jj < 6; jj++) {
            int cc = cbase + jj;
            bool ok = ((unsigned)cc < 256u);
            #pragma unroll
            for (int r = 0; r < 6; r++) d[r][jj] = ok ? rows[rl + r][cc] : 0.f;
        }
        float t[6][6];
        #pragma unroll
        for (int c2 = 0; c2 < 6; c2++) {
            float tc[6];
            bt6(d[0][c2], d[1][c2], d[2][c2], d[3][c2], d[4][c2], d[5][c2], tc);
            #pragma unroll
            for (int r = 0; r < 6; r++) t[r][c2] = tc[r];
        }
        int tlin = ty*NT4 + tx;
        #pragma unroll
        for (int r = 0; r < 6; r++) {
            float vr[6];
            bt6(t[r][0], t[r][1], t[r][2], t[r][3], t[r][4], t[r][5], vr);
            #pragma unroll
            for (int c2 = 0; c2 < 6; c2++)
                g_V[((b*NF + r*6+c2)*64 + ci)*TS4 + tlin] = vr[c2];
        }
    }
}

// ---------------------------------------------------------------------------
// Per-frequency GEMM, single-stage full-K smem, big thread tile:
//   M[bf][co][t] = sum_ci U[f][ci][co] * V[bf][ci][t].
// Block: 128 threads, 64 co x 128 t; thread: 8 co x 8 t (64 acc).
__global__ __launch_bounds__(128, 3) void winograd_gemm() {
    __shared__ float Vs[64][128];    // 32 KB
    __shared__ float Us[64][64];     // 16 KB
    int bf = blockIdx.x / NBLK4;     // b*36 + f
    int tc = blockIdx.x % NBLK4;
    int f  = bf % NF;
    int t0 = tc * 128;
    int tid = threadIdx.x;
    int cg = tid >> 4, tg = tid & 15;

    // ---- stage whole K slab ----
    {
        const float* vsrc = &g_V[(size_t)(bf*64)*TS4 + t0];
        #pragma unroll
        for (int i = 0; i < 16; i++) {
            int lin = tid + i*128;           // 0..2047 float4 units
            int r = lin >> 5, c = lin & 31;
            *(float4*)&Vs[r][c*4] = *(const float4*)(vsrc + (size_t)r*TS4 + c*4);
        }
        const float* usrc = &g_U[f*4096];
        #pragma unroll
        for (int i = 0; i < 8; i++) {
            int lin = tid + i*128;           // 0..1023 float4 units
            int r = lin >> 4, c = lin & 15;
            *(float4*)&Us[r][c*4] = *(const float4*)(usrc + r*64 + c*4);
        }
    }
    __syncthreads();

    float acc[8][8];
    #pragma unroll
    for (int i = 0; i < 8; i++)
        #pragma unroll
        for (int j = 0; j < 8; j++) acc[i][j] = 0.f;

    #pragma unroll 4
    for (int cl = 0; cl < 64; cl++) {
        float4 w0 = *(const float4*)&Us[cl][cg*8];
        float4 w1 = *(const float4*)&Us[cl][cg*8 + 4];
        float4 s0 = *(const float4*)&Vs[cl][tg*8];
        float4 s1 = *(const float4*)&Vs[cl][tg*8 + 4];
        float wv[8] = {w0.x, w0.y, w0.z, w0.w, w1.x, w1.y, w1.z, w1.w};
        float sv[8] = {s0.x, s0.y, s0.z, s0.w, s1.x, s1.y, s1.z, s1.w};
        #pragma unroll
        for (int i = 0; i < 8; i++)
            #pragma unroll
            for (int j = 0; j < 8; j++)
                acc[i][j] += wv[i]*sv[j];
    }

    #pragma unroll
    for (int i = 0; i < 8; i++) {
        float* mp = &g_M[(size_t)(bf*64 + cg*8 + i)*TS4 + t0 + tg*8];
        *(float4*)mp       = make_float4(acc[i][0], acc[i][1], acc[i][2], acc[i][3]);
        *(float4*)(mp + 4) = make_float4(acc[i][4], acc[i][5], acc[i][6], acc[i][7]);
    }
}

// ---------------------------------------------------------------------------
// Output transform: Y = A^T m A (4x4 outputs) -> dense conv on extended grid.
__global__ __launch_bounds__(128) void winograd_out() {
    int z  = blockIdx.x;
    int ty = z % NT4;
    int bc = z / NT4;                // b*64 + co
    int tid = threadIdx.x;
    int b = bc >> 6;

    int tx = tid;
    if (tx >= NT4) return;
    int tlin = ty*NT4 + tx;
    float m[6][6];
    #pragma unroll
    for (int f = 0; f < NF; f++)
        m[f/6][f%6] = g_M[((b*NF + f)*64 + (bc & 63))*TS4 + tlin];

    float t2[4][6];
    #pragma unroll
    for (int c2 = 0; c2 < 6; c2++) {
        float m0 = m[0][c2], m1 = m[1][c2], m2 = m[2][c2];
        float m3 = m[3][c2], m4 = m[4][c2], m5 = m[5][c2];
        t2[0][c2] = m0 + m1 + m2 + m3 + m4;
        t2[1][c2] = m1 - m2 + 2.f*(m3 - m4);
        t2[2][c2] = m1 + m2 + 4.f*(m3 + m4);
        t2[3][c2] = m1 - m2 + 8.f*(m3 - m4) + m5;
    }
    float* gbase = &g_winG[((size_t)bc*GP4 + 4*ty)*GP4 + 4*tx];
    #pragma unroll
    for (int r = 0; r < 4; r++) {
        float a0 = t2[r][0], a1 = t2[r][1], a2 = t2[r][2];
        float a3 = t2[r][3], a4 = t2[r][4], a5 = t2[r][5];
        float y0 = a0 + a1 + a2 + a3 + a4;
        float y1 = a1 - a2 + 2.f*(a3 - a4);
        float y2 = a1 + a2 + 4.f*(a3 + a4);
        float y3 = a1 - a2 + 8.f*(a3 - a4) + a5;
        *(float4*)(gbase + r*GP4) = make_float4(y0, y1, y2, y3);
    }
}

// ---------------------------------------------------------------------------
// Flow-guided bilinear resample of G -> deform conv output.
__global__ __launch_bounds__(256) void resample_kernel(
    const float* __restrict__ u, const float* __restrict__ v)
{
    int idx = blockIdx.x*256 + threadIdx.x;
    int b = idx >> 16, p = idx & 65535;
    int y = p >> 8, x = p & 255;
    float py  = (float)y + v[b*S + p];
    float px_ = (float)x + u[b*S + p];
    float fy = floorf(py), fx = floorf(px_);
    int y0 = (int)fy, x0 = (int)fx;
    float wy = py - fy, wx = px_ - fx;
    bool r0 = ((unsigned)(y0+1) < (unsigned)GRV);
    bool r1 = ((unsigned)(y0+2) < (unsigned)GRV);
    bool c0 = ((unsigned)(x0+1) < (unsigned)GRV);
    bool c1 = ((unsigned)(x0+2) < (unsigned)GRV);
    int off = (y0+1)*GP4 + (x0+1);
    float w00 = (1.f-wy)*(1.f-wx), w01 = (1.f-wy)*wx;
    float w10 = wy*(1.f-wx),       w11 = wy*wx;

    const float* Gb = g_winG + (size_t)(b*64)*GP4*GP4;
    float* dst = &g_conv[(size_t)(b*64)*S + p];
    #pragma unroll 4
    for (int ch = 0; ch < 64; ch++) {
        const float* Gp = Gb + (size_t)ch*GP4*GP4;
        float g00 = (r0 && c0) ? __ldg(Gp + off)         : 0.f;
        float g01 = (r0 && c1) ? __ldg(Gp + off + 1)     : 0.f;
        float g10 = (r1 && c0) ? __ldg(Gp + off + GP4)   : 0.f;
        float g11 = (r1 && c1) ? __ldg(Gp + off + GP4+1) : 0.f;
        dst[(size_t)ch*S] = w00*g00 + w01*g01 + w10*g10 + w11*g11;
    }
}

// ---------------------------------------------------------------------------
// Gram + norms (unchanged).
__global__ __launch_bounds__(256) void dots_kernel(const float* __restrict__ xg) {
    __shared__ float qs[16][260];
    __shared__ float ks[16][260];
    __shared__ float s_nq[16], s_nk[16];

    int tid = threadIdx.x;
    int bh  = blockIdx.x >> 5;
    int sl  = blockIdx.x & 31;
    int b   = bh >> 2, hh = bh & 3;
    int i = tid >> 4, j = tid & 15;
    int s0 = sl * 2048;

    if (tid < 16) { s_nq[tid] = 0.f; s_nk[tid] = 0.f; }

    float g = 0.f, nqp = 0.f, nkp = 0.f;
    for (int ch = 0; ch < 8; ++ch) {
        __syncthreads();
        int sbase = s0 + ch*256;
        #pragma unroll
        for (int e = 0; e < 8; ++e) {
            int lin = tid + e*256;
            int r = lin >> 6, c4 = lin & 63;
            const float* src = (r < 16)
                ? (xg     + (b*C + hh*HD + r)*S)
                : (g_conv + (b*C + hh*HD + (r-16))*S);
            float4 val = *(const float4*)(src + sbase + c4*4);
            float* dst = (r < 16) ? &qs[r][c4*4] : &ks[r-16][c4*4];
            dst[0] = val.x; dst[1] = val.y; dst[2] = val.z; dst[3] = val.w;
        }
        __syncthreads();
        #pragma unroll 8
        for (int s = 0; s < 256; s += 4) {
            float4 qv = *(const float4*)&qs[i][s];
            float4 kv = *(const float4*)&ks[j][s];
            g += qv.x*kv.x; g += qv.y*kv.y; g += qv.z*kv.z; g += qv.w*kv.w;
        }
        #pragma unroll 4
        for (int s = j; s < 256; s += 16) { float q0 = qs[i][s]; nqp += q0*q0; }
        #pragma unroll 4
        for (int s = i; s < 256; s += 16) { float k0 = ks[j][s]; nkp += k0*k0; }
    }
    atomicAdd(&g_gram[bh*256 + i*16 + j], g);
    atomicAdd(&s_nq[i], nqp);
    atomicAdd(&s_nk[j], nkp);
    __syncthreads();
    if (tid < 16)       atomicAdd(&g_qn2[bh*16 + tid], s_nq[tid]);
    else if (tid < 32)  atomicAdd(&g_kn2[bh*16 + tid-16], s_nk[tid-16]);
}

// ---------------------------------------------------------------------------
// Fused softmax + out.
__global__ __launch_bounds__(256, 2) void out_kernel(float* __restrict__ out,
                                                     const float* __restrict__ temp) {
    __shared__ float s_attn[16][16];
    int tid = threadIdx.x;
    int bh  = blockIdx.x >> 6;
    int tile = blockIdx.x & 63;
    int b = bh >> 2, hh = bh & 3;

    {
        int i = tid >> 4, j = tid & 15;
        float dq = fmaxf(sqrtf(g_qn2[bh*16 + i]), 1e-12f);
        float dk = fmaxf(sqrtf(g_kn2[bh*16 + j]), 1e-12f);
        float T  = temp[hh];
        float l  = g_gram[bh*256 + i*16 + j] / (dq*dk) * T;
        float m = l;
        #pragma unroll
        for (int off = 8; off > 0; off >>= 1)
            m = fmaxf(m, __shfl_xor_sync(0xffffffffu, m, off, 16));
        float e = expf(l - m);
        float ssum = e;
        #pragma unroll
        for (int off = 8; off > 0; off >>= 1)
            ssum += __shfl_xor_sync(0xffffffffu, ssum, off, 16);
        s_attn[i][j] = e / ssum;
    }
    __syncthreads();

    int s = tile*1024 + tid*4;
    float4 acc[16];
    #pragma unroll
    for (int o = 0; o < 16; o++) acc[o] = make_float4(0.f, 0.f, 0.f, 0.f);

    #pragma unroll
    for (int d = 0; d < 16; d++) {
        float4 kvv = *(const float4*)&g_conv[(b*C + hh*HD + d)*S + s];
        #pragma unroll
        for (int o = 0; o < 16; o++) {
            float a = s_attn[o][d];
            acc[o].x += a*kvv.x; acc[o].y += a*kvv.y;
            acc[o].z += a*kvv.z; acc[o].w += a*kvv.w;
        }
    }
    #pragma unroll
    for (int o = 0; o < 16; o++)
        *(float4*)&out[(b*C + hh*HD + o)*S + s] = acc[o];
}

// ---------------------------------------------------------------------------
extern "C" void kernel_launch(void* const* d_in, const int* in_sizes, int n_in,
                              void* d_out, int out_size) {
    const float* clone  = (const float*)d_in[0];
    const float* xg     = (const float*)d_in[1];
    const float* u      = (const float*)d_in[2];
    const float* v      = (const float*)d_in[3];
    const float* weight = (const float*)d_in[4];
    const float* temp   = (const float*)d_in[5];
    float* out = (float*)d_out;

    prep_kernel<<<16, 256>>>(weight);
    winograd_in<<<Bn*64*NTYG, 256>>>(clone);
    winograd_gemm<<<Bn*NF*NBLK4, 128>>>();
    winograd_out<<<Bn*64*NT4, 128>>>();
    resample_kernel<<<Bn*S/256, 256>>>(u, v);
    dots_kernel<<<Bn*HEADS*32, 256>>>(xg);
    out_kernel<<<Bn*HEADS*64, 256>>>(out, temp);
}

// round 13
// speedup vs baseline: 3.2384x; 1.0668x over previous
#include <cuda_runtime.h>
#include <math.h>
#include <stdint.h>

#define Bn 2
#define C 64
#define H 256
#define W 256
#define S (H*W)
#define HEADS 4
#define HD 16

#define NT6 43           // F(6x6) tiles per dim: 43*6 = 258 = ext grid exactly
#define NTT6 (NT6*NT6)   // 1849 tiles
#define TS6 1920         // tile stride (15*128)
#define NBLK6 15         // gemm 128-tile blocks per (b,f)
#define NF6 64           // frequencies (8x8)
#define GRV 258          // valid ext-grid rows/cols
#define GP 260           // winG row stride
#define NTYG6 8          // in-transform: groups of 6 ty rows (covers 48>=43)
#define NTYGO 15         // out-transform: groups of 3 ty rows (covers 45>=43)

// Scratch (device globals -- no allocations allowed; zero-initialized)
__device__ float g_conv[Bn*C*S];
__device__ float g_gram[Bn*HEADS*HD*HD];
__device__ float g_qn2[Bn*HEADS*HD];
__device__ float g_kn2[Bn*HEADS*HD];
__device__ __align__(16) float g_U[NF6*64*64];       // [f][ci][co]  4MB
__device__ __align__(16) float g_V[Bn*NF6*64*TS6];   // [b][f][ci][t] ~63MB
__device__ __align__(16) float g_M[Bn*NF6*64*TS6];   // [b][f][co][t] ~63MB
__device__ __align__(16) float g_winG[Bn*64*GP*GP];

// ---------------------------------------------------------------------------
// B^T (F(6,3), points 0,±1,±2,±1/2) applied to 8-vector. (verified: const+ramp)
__device__ __forceinline__ void bt8(const float* d, float* t) {
    t[0] =  d[0] - 5.25f*d[2] + 5.25f*d[4] - d[6];
    t[1] =  d[1] + d[2] - 4.25f*(d[3] + d[4]) + d[5] + d[6];
    t[2] = -d[1] + d[2] + 4.25f*(d[3] - d[4]) - d[5] + d[6];
    t[3] =  0.5f*d[1] + 0.25f*d[2] - 2.5f*d[3] - 1.25f*d[4] + 2.f*d[5] + d[6];
    t[4] = -0.5f*d[1] + 0.25f*d[2] + 2.5f*d[3] - 1.25f*d[4] - 2.f*d[5] + d[6];
    t[5] =  2.f*d[1] + 4.f*d[2] - 2.5f*d[3] - 5.f*d[4] + 0.5f*d[5] + d[6];
    t[6] = -2.f*d[1] + 4.f*d[2] + 2.5f*d[3] - 5.f*d[4] - 0.5f*d[5] + d[6];
    t[7] = -d[1] + 5.25f*d[3] - 5.25f*d[5] + d[7];
}
// G (8x3) applied to 3-vector.
__device__ __forceinline__ void g8(float g0, float g1, float g2, float* u) {
    u[0] = g0;
    u[1] = (-2.f/9.f)*(g0 + g1 + g2);
    u[2] = (-2.f/9.f)*(g0 - g1 + g2);
    u[3] = (1.f/90.f)*g0 + (1.f/45.f)*g1 + (2.f/45.f)*g2;
    u[4] = (1.f/90.f)*g0 - (1.f/45.f)*g1 + (2.f/45.f)*g2;
    u[5] = (32.f/45.f)*g0 + (16.f/45.f)*g1 + (8.f/45.f)*g2;
    u[6] = (32.f/45.f)*g0 - (16.f/45.f)*g1 + (8.f/45.f)*g2;
    u[7] = g2;
}
// A^T (6x8) applied to 8-vector.
__device__ __forceinline__ void at6(const float* m, float* y) {
    float p12 = m[1]+m[2], m12 = m[1]-m[2];
    float p34 = m[3]+m[4], m34 = m[3]-m[4];
    float p56 = m[5]+m[6], m56 = m[5]-m[6];
    y[0] = m[0] + p12 + p34 + p56;
    y[1] = m12 + 2.f*m34 + 0.5f*m56;
    y[2] = p12 + 4.f*p34 + 0.25f*p56;
    y[3] = m12 + 8.f*m34 + 0.125f*m56;
    y[4] = p12 + 16.f*p34 + 0.0625f*p56;
    y[5] = m12 + 32.f*m34 + 0.03125f*m56 + m[7];
}

// ---------------------------------------------------------------------------
// Prep: U = G g G^T (8x8 per (ci,co)); zero gram accumulators.
__global__ void prep_kernel(const float* __restrict__ weight) {
    int t = blockIdx.x*256 + threadIdx.x;        // 0..4095
    if (t < 4096) {
        int co = t & 63, ci = t >> 6;
        float g[3][3];
        #pragma unroll
        for (int k = 0; k < 9; k++) g[k/3][k%3] = weight[(co*C + ci)*9 + k];
        float q[8][3];
        #pragma unroll
        for (int c = 0; c < 3; c++) {
            float col[8];
            g8(g[0][c], g[1][c], g[2][c], col);
            #pragma unroll
            for (int r = 0; r < 8; r++) q[r][c] = col[r];
        }
        #pragma unroll
        for (int r = 0; r < 8; r++) {
            float ur[8];
            g8(q[r][0], q[r][1], q[r][2], ur);
            #pragma unroll
            for (int c = 0; c < 8; c++)
                g_U[(r*8+c)*4096 + ci*64 + co] = ur[c];
        }
    }
    if (blockIdx.x == 0) {
        int tid = threadIdx.x;
        for (int k = tid; k < Bn*HEADS*HD*HD; k += 256) g_gram[k] = 0.f;
        for (int k = tid; k < Bn*HEADS*HD;    k += 256) { g_qn2[k] = 0.f; g_kn2[k] = 0.f; }
    }
}

// ---------------------------------------------------------------------------
// Input transform: V = B^T d B per 8x8 tile (stride 6, zero-padded clone).
// Block = (b*64+ci)*NTYG6 + tyg; 6 ty rows x 43 tx = 258 tasks over 256 thr.
__global__ __launch_bounds__(256) void winograd_in(const float* __restrict__ clone) {
    __shared__ float rows[38][256];
    int z   = blockIdx.x;
    int tyg = z % NTYG6;
    int bc  = z / NTYG6;             // b*64 + ci
    int ci  = bc & 63, b = bc >> 6;
    int tid = threadIdx.x;

    const float* plane = clone + ((size_t)bc << 16);
    int gr0 = 36*tyg - 2;
    for (int i = tid; i < 38*64; i += 256) {
        int r = i >> 6, c4 = i & 63;
        int gr = gr0 + r;
        float4 val = make_float4(0.f,0.f,0.f,0.f);
        if ((unsigned)gr < 256u) val = *(const float4*)(plane + gr*256 + c4*4);
        *(float4*)&rows[r][c4*4] = val;
    }
    __syncthreads();

    for (int task = tid; task < 6*NT6; task += 256) {
        int tyl = task / NT6;            // 0..5
        int tx  = task - tyl*NT6;
        int ty  = 6*tyg + tyl;
        if (ty >= NT6) continue;
        float d[8][8];
        int cbase = 6*tx - 2;
        int rl = 6*tyl;                  // smem row offset: (6ty-2)-(36tyg-2)
        #pragma unroll
        for (int jj = 0; jj < 8; jj++) {
            int cc = cbase + jj;
            bool ok = ((unsigned)cc < 256u);
            #pragma unroll
            for (int r = 0; r < 8; r++) d[r][jj] = ok ? rows[rl + r][cc] : 0.f;
        }
        float t[8][8];
        #pragma unroll
        for (int c2 = 0; c2 < 8; c2++) {
            float dc[8], tc[8];
            #pragma unroll
            for (int r = 0; r < 8; r++) dc[r] = d[r][c2];
            bt8(dc, tc);
            #pragma unroll
            for (int r = 0; r < 8; r++) t[r][c2] = tc[r];
        }
        int tlin = ty*NT6 + tx;
        #pragma unroll
        for (int r = 0; r < 8; r++) {
            float vr[8];
            bt8(t[r], vr);
            #pragma unroll
            for (int c2 = 0; c2 < 8; c2++)
                g_V[((b*NF6 + r*8+c2)*64 + ci)*TS6 + tlin] = vr[c2];
        }
    }
}

// ---------------------------------------------------------------------------
// Per-frequency GEMM, single-stage full-K smem, 8co x 8t thread tile.
__global__ __launch_bounds__(128, 3) void winograd_gemm() {
    __shared__ float Vs[64][128];    // 32 KB
    __shared__ float Us[64][64];     // 16 KB
    int bf = blockIdx.x / NBLK6;     // b*64 + f
    int tc = blockIdx.x % NBLK6;
    int f  = bf & 63;
    int t0 = tc * 128;
    int tid = threadIdx.x;
    int cg = tid >> 4, tg = tid & 15;

    {
        const float* vsrc = &g_V[(size_t)(bf*64)*TS6 + t0];
        #pragma unroll
        for (int i = 0; i < 16; i++) {
            int lin = tid + i*128;
            int r = lin >> 5, c = lin & 31;
            *(float4*)&Vs[r][c*4] = *(const float4*)(vsrc + (size_t)r*TS6 + c*4);
        }
        const float* usrc = &g_U[f*4096];
        #pragma unroll
        for (int i = 0; i < 8; i++) {
            int lin = tid + i*128;
            int r = lin >> 4, c = lin & 15;
            *(float4*)&Us[r][c*4] = *(const float4*)(usrc + r*64 + c*4);
        }
    }
    __syncthreads();

    float acc[8][8];
    #pragma unroll
    for (int i = 0; i < 8; i++)
        #pragma unroll
        for (int j = 0; j < 8; j++) acc[i][j] = 0.f;

    #pragma unroll 4
    for (int cl = 0; cl < 64; cl++) {
        float4 w0 = *(const float4*)&Us[cl][cg*8];
        float4 w1 = *(const float4*)&Us[cl][cg*8 + 4];
        float4 s0 = *(const float4*)&Vs[cl][tg*8];
        float4 s1 = *(const float4*)&Vs[cl][tg*8 + 4];
        float wv[8] = {w0.x, w0.y, w0.z, w0.w, w1.x, w1.y, w1.z, w1.w};
        float sv[8] = {s0.x, s0.y, s0.z, s0.w, s1.x, s1.y, s1.z, s1.w};
        #pragma unroll
        for (int i = 0; i < 8; i++)
            #pragma unroll
            for (int j = 0; j < 8; j++)
                acc[i][j] += wv[i]*sv[j];
    }

    #pragma unroll
    for (int i = 0; i < 8; i++) {
        float* mp = &g_M[(size_t)(bf*64 + cg*8 + i)*TS6 + t0 + tg*8];
        *(float4*)mp       = make_float4(acc[i][0], acc[i][1], acc[i][2], acc[i][3]);
        *(float4*)(mp + 4) = make_float4(acc[i][4], acc[i][5], acc[i][6], acc[i][7]);
    }
}

// ---------------------------------------------------------------------------
// Output transform: Y = A^T m A (6x6 outputs) -> dense conv on extended grid.
// Block = (b*64+co)*NTYGO + tyg; 3 ty rows x 43 tx = 129 tasks over 128 thr.
__global__ __launch_bounds__(128) void winograd_out() {
    int z   = blockIdx.x;
    int tyg = z % NTYGO;
    int bc  = z / NTYGO;             // b*64 + co
    int co  = bc & 63, b = bc >> 6;
    int tid = threadIdx.x;

    for (int task = tid; task < 3*NT6; task += 128) {
        int tyl = task / NT6;
        int tx  = task - tyl*NT6;
        int ty  = 3*tyg + tyl;
        if (ty >= NT6) continue;
        int tlin = ty*NT6 + tx;
        float m[8][8];
        #pragma unroll
        for (int f = 0; f < NF6; f++)
            m[f >> 3][f & 7] = g_M[((b*NF6 + f)*64 + co)*TS6 + tlin];

        float t2[6][8];
        #pragma unroll
        for (int c2 = 0; c2 < 8; c2++) {
            float mc[8], yc[6];
            #pragma unroll
            for (int r = 0; r < 8; r++) mc[r] = m[r][c2];
            at6(mc, yc);
            #pragma unroll
            for (int r = 0; r < 6; r++) t2[r][c2] = yc[r];
        }
        float* gbase = &g_winG[((size_t)bc*GP + 6*ty)*GP + 6*tx];
        #pragma unroll
        for (int r = 0; r < 6; r++) {
            float y[6];
            at6(t2[r], y);
            float* gp = gbase + r*GP;
            *(float2*)(gp)     = make_float2(y[0], y[1]);
            *(float2*)(gp + 2) = make_float2(y[2], y[3]);
            *(float2*)(gp + 4) = make_float2(y[4], y[5]);
        }
    }
}

// ---------------------------------------------------------------------------
// Flow-guided bilinear resample of G -> deform conv output.
__global__ __launch_bounds__(256) void resample_kernel(
    const float* __restrict__ u, const float* __restrict__ v)
{
    int idx = blockIdx.x*256 + threadIdx.x;
    int b = idx >> 16, p = idx & 65535;
    int y = p >> 8, x = p & 255;
    float py  = (float)y + v[b*S + p];
    float px_ = (float)x + u[b*S + p];
    float fy = floorf(py), fx = floorf(px_);
    int y0 = (int)fy, x0 = (int)fx;
    float wy = py - fy, wx = px_ - fx;
    bool r0 = ((unsigned)(y0+1) < (unsigned)GRV);
    bool r1 = ((unsigned)(y0+2) < (unsigned)GRV);
    bool c0 = ((unsigned)(x0+1) < (unsigned)GRV);
    bool c1 = ((unsigned)(x0+2) < (unsigned)GRV);
    int off = (y0+1)*GP + (x0+1);
    float w00 = (1.f-wy)*(1.f-wx), w01 = (1.f-wy)*wx;
    float w10 = wy*(1.f-wx),       w11 = wy*wx;

    const float* Gb = g_winG + (size_t)(b*64)*GP*GP;
    float* dst = &g_conv[(size_t)(b*64)*S + p];
    #pragma unroll 4
    for (int ch = 0; ch < 64; ch++) {
        const float* Gp = Gb + (size_t)ch*GP*GP;
        float g00 = (r0 && c0) ? __ldg(Gp + off)        : 0.f;
        float g01 = (r0 && c1) ? __ldg(Gp + off + 1)    : 0.f;
        float g10 = (r1 && c0) ? __ldg(Gp + off + GP)   : 0.f;
        float g11 = (r1 && c1) ? __ldg(Gp + off + GP+1) : 0.f;
        dst[(size_t)ch*S] = w00*g00 + w01*g01 + w10*g10 + w11*g11;
    }
}

// ---------------------------------------------------------------------------
// Gram + norms (unchanged).
__global__ __launch_bounds__(256) void dots_kernel(const float* __restrict__ xg) {
    __shared__ float qs[16][260];
    __shared__ float ks[16][260];
    __shared__ float s_nq[16], s_nk[16];

    int tid = threadIdx.x;
    int bh  = blockIdx.x >> 5;
    int sl  = blockIdx.x & 31;
    int b   = bh >> 2, hh = bh & 3;
    int i = tid >> 4, j = tid & 15;
    int s0 = sl * 2048;

    if (tid < 16) { s_nq[tid] = 0.f; s_nk[tid] = 0.f; }

    float g = 0.f, nqp = 0.f, nkp = 0.f;
    for (int ch = 0; ch < 8; ++ch) {
        __syncthreads();
        int sbase = s0 + ch*256;
        #pragma unroll
        for (int e = 0; e < 8; ++e) {
            int lin = tid + e*256;
            int r = lin >> 6, c4 = lin & 63;
            const float* src = (r < 16)
                ? (xg     + (b*C + hh*HD + r)*S)
                : (g_conv + (b*C + hh*HD + (r-16))*S);
            float4 val = *(const float4*)(src + sbase + c4*4);
            float* dst = (r < 16) ? &qs[r][c4*4] : &ks[r-16][c4*4];
            dst[0] = val.x; dst[1] = val.y; dst[2] = val.z; dst[3] = val.w;
        }
        __syncthreads();
        #pragma unroll 8
        for (int s = 0; s < 256; s += 4) {
            float4 qv = *(const float4*)&qs[i][s];
            float4 kv = *(const float4*)&ks[j][s];
            g += qv.x*kv.x; g += qv.y*kv.y; g += qv.z*kv.z; g += qv.w*kv.w;
        }
        #pragma unroll 4
        for (int s = j; s < 256; s += 16) { float q0 = qs[i][s]; nqp += q0*q0; }
        #pragma unroll 4
        for (int s = i; s < 256; s += 16) { float k0 = ks[j][s]; nkp += k0*k0; }
    }
    atomicAdd(&g_gram[bh*256 + i*16 + j], g);
    atomicAdd(&s_nq[i], nqp);
    atomicAdd(&s_nk[j], nkp);
    __syncthreads();
    if (tid < 16)       atomicAdd(&g_qn2[bh*16 + tid], s_nq[tid]);
    else if (tid < 32)  atomicAdd(&g_kn2[bh*16 + tid-16], s_nk[tid-16]);
}

// ---------------------------------------------------------------------------
// Fused softmax + out; float2 columns for occupancy (16 float2 accs).
__global__ __launch_bounds__(256) void out_kernel(float* __restrict__ out,
                                                  const float* __restrict__ temp) {
    __shared__ float s_attn[16][16];
    int tid = threadIdx.x;
    int bh  = blockIdx.x >> 7;     // 128 tiles of 512 px
    int tile = blockIdx.x & 127;
    int b = bh >> 2, hh = bh & 3;

    {
        int i = tid >> 4, j = tid & 15;
        float dq = fmaxf(sqrtf(g_qn2[bh*16 + i]), 1e-12f);
        float dk = fmaxf(sqrtf(g_kn2[bh*16 + j]), 1e-12f);
        float T  = temp[hh];
        float l  = g_gram[bh*256 + i*16 + j] / (dq*dk) * T;
        float m = l;
        #pragma unroll
        for (int off = 8; off > 0; off >>= 1)
            m = fmaxf(m, __shfl_xor_sync(0xffffffffu, m, off, 16));
        float e = expf(l - m);
        float ssum = e;
        #pragma unroll
        for (int off = 8; off > 0; off >>= 1)
            ssum += __shfl_xor_sync(0xffffffffu, ssum, off, 16);
        s_attn[i][j] = e / ssum;
    }
    __syncthreads();

    int s = tile*512 + tid*2;
    float2 acc[16];
    #pragma unroll
    for (int o = 0; o < 16; o++) acc[o] = make_float2(0.f, 0.f);

    #pragma unroll
    for (int d = 0; d < 16; d++) {
        float2 kvv = *(const float2*)&g_conv[(b*C + hh*HD + d)*S + s];
        #pragma unroll
        for (int o = 0; o < 16; o++) {
            float a = s_attn[o][d];
            acc[o].x += a*kvv.x; acc[o].y += a*kvv.y;
        }
    }
    #pragma unroll
    for (int o = 0; o < 16; o++)
        *(float2*)&out[(b*C + hh*HD + o)*S + s] = acc[o];
}

// ---------------------------------------------------------------------------
extern "C" void kernel_launch(void* const* d_in, const int* in_sizes, int n_in,
                              void* d_out, int out_size) {
    const float* clone  = (const float*)d_in[0];
    const float* xg     = (const float*)d_in[1];
    const float* u      = (const float*)d_in[2];
    const float* v      = (const float*)d_in[3];
    const float* weight = (const float*)d_in[4];
    const float* temp   = (const float*)d_in[5];
    float* out = (float*)d_out;

    prep_kernel<<<16, 256>>>(weight);
    winograd_in<<<Bn*64*NTYG6, 256>>>(clone);
    winograd_gemm<<<Bn*NF6*NBLK6, 128>>>();
    winograd_out<<<Bn*64*NTYGO, 128>>>();
    resample_kernel<<<Bn*S/256, 256>>>(u, v);
    dots_kernel<<<Bn*HEADS*32, 256>>>(xg);
    out_kernel<<<Bn*HEADS*128, 256>>>(out, temp);
}